// round 9
// baseline (speedup 1.0000x reference)
#include <cuda_runtime.h>
#include <cuda_bf16.h>
#include <math.h>
#include <cstdint>

#define BQ   2
#define SQ   2048
#define DIM  1024
#define HQ   16
#define DH   64
#define GQ   16
#define IQ   256
#define MROW (BQ*SQ)   /* 4096 */

// scores*0.125 folded into Q together with log2(e) so softmax uses raw ex2
#define QSCALE 0.18033688011112042f   /* 0.125 * log2(e) */

// ---------------- device scratch (no allocations allowed) ----------------
__device__ __nv_bfloat16 g_wh[4][DIM*DIM];   // W_eff hi, [n][k]
__device__ __nv_bfloat16 g_wl[4][DIM*DIM];   // W_eff lo
__device__ __nv_bfloat16 g_ah[MROW*DIM];     // activation hi (x, later attn out)
__device__ __nv_bfloat16 g_al[MROW*DIM];     // activation lo
__device__ __nv_bfloat16 g_qh[MROW*DIM];
__device__ __nv_bfloat16 g_ql[MROW*DIM];
__device__ __nv_bfloat16 g_kh[MROW*DIM];
__device__ __nv_bfloat16 g_kl[MROW*DIM];
__device__ __nv_bfloat16 g_vh[MROW*DIM];
__device__ __nv_bfloat16 g_vl[MROW*DIM];

// ---------------- helpers --------------------------------------------------
__device__ __forceinline__ uint32_t smem_to_u32(const void* p) {
    uint32_t a;
    asm("{ .reg .u64 t; cvta.to.shared.u64 t, %1; cvt.u32.u64 %0, t; }"
        : "=r"(a) : "l"(p));
    return a;
}
__device__ __forceinline__ void cp_async16(uint32_t dst, const void* src) {
    asm volatile("cp.async.ca.shared.global [%0], [%1], 16;"
                 :: "r"(dst), "l"(src));
}
#define CP_COMMIT() asm volatile("cp.async.commit_group;" ::: "memory")
#define CP_WAIT(n)  asm volatile("cp.async.wait_group %0;" :: "n"(n) : "memory")

__device__ __forceinline__ float ex2f(float x) {
    float r;
    asm("ex2.approx.f32 %0, %1;" : "=f"(r) : "f"(x));
    return r;
}

// split fp32 pair into bf16x2 hi (x low half, y high half) and lo
__device__ __forceinline__ void split2(float x, float y, uint32_t& hi, uint32_t& lo) {
    uint32_t h;
    asm("cvt.rn.bf16x2.f32 %0, %1, %2;" : "=r"(h) : "f"(y), "f"(x));
    float xh = __uint_as_float(h << 16);
    float yh = __uint_as_float(h & 0xFFFF0000u);
    float xl = x - xh, yl = y - yh;
    uint32_t l;
    asm("cvt.rn.bf16x2.f32 %0, %1, %2;" : "=r"(l) : "f"(yl), "f"(xl));
    hi = h; lo = l;
}

__device__ __forceinline__ void mma16816(float* c, const uint32_t* a, const uint32_t* b) {
    asm volatile(
        "mma.sync.aligned.m16n8k16.row.col.f32.bf16.bf16.f32 "
        "{%0,%1,%2,%3}, {%4,%5,%6,%7}, {%8,%9}, {%0,%1,%2,%3};"
        : "+f"(c[0]), "+f"(c[1]), "+f"(c[2]), "+f"(c[3])
        : "r"(a[0]), "r"(a[1]), "r"(a[2]), "r"(a[3]), "r"(b[0]), "r"(b[1]));
}
__device__ __forceinline__ void ldmatrix_x4(uint32_t* r, uint32_t addr) {
    asm volatile("ldmatrix.sync.aligned.m8n8.x4.shared.b16 {%0,%1,%2,%3}, [%4];"
                 : "=r"(r[0]), "=r"(r[1]), "=r"(r[2]), "=r"(r[3]) : "r"(addr));
}
__device__ __forceinline__ void ldmatrix_x2(uint32_t* r, uint32_t addr) {
    asm volatile("ldmatrix.sync.aligned.m8n8.x2.shared.b16 {%0,%1}, [%2];"
                 : "=r"(r[0]), "=r"(r[1]) : "r"(addr));
}
__device__ __forceinline__ void ldmatrix_x2_trans(uint32_t* r, uint32_t addr) {
    asm volatile("ldmatrix.sync.aligned.m8n8.x2.trans.shared.b16 {%0,%1}, [%2];"
                 : "=r"(r[0]), "=r"(r[1]) : "r"(addr));
}

// quaternion rope rotation (reference math, fp32)
__device__ __forceinline__ void qrot(float cs, float sn, int ax,
                                     float xr, float xi, float xj, float xk,
                                     float& pr, float& pi, float& pj, float& pk) {
    float ui = (ax == 0) ? sn : 0.f;
    float uj = (ax == 1) ? sn : 0.f;
    float uk = (ax == 2) ? sn : 0.f;
    pr = cs * xr - ui * xi - uj * xj - uk * xk;
    pi = cs * xi + ui * xr + uj * xk - uk * xj;
    pj = cs * xj - ui * xk + uj * xr + uk * xi;
    pk = cs * xk + ui * xj - uj * xi + uk * xr;
}

// ---------------- build all 4 effective quaternion weights -----------------
struct WPtrs { const float* w[4][4]; };   // [proj][comp r,i,j,k]
__global__ void build_w_all_kernel(WPtrs wp,
                                   __nv_bfloat16* __restrict__ WhBase,
                                   __nv_bfloat16* __restrict__ WlBase) {
    int proj = blockIdx.y;
    int idx = blockIdx.x * blockDim.x + threadIdx.x;   // 0 .. DIM*IQ-1
    int n = idx >> 8;          // 0..1023
    int p = idx & 255;         // 0..255
    int m = n >> 2, c = n & 3;

    int off = m * IQ + p;
    float r = wp.w[proj][0][off], i = wp.w[proj][1][off];
    float j = wp.w[proj][2][off], k = wp.w[proj][3][off];

    float v0, v1, v2, v3;
    switch (c) {
        case 0: v0 =  r; v1 = -i; v2 = -j; v3 = -k; break;
        case 1: v0 =  i; v1 =  r; v2 = -j; v3 =  k; break;
        case 2: v0 =  j; v1 =  i; v2 =  r; v3 = -k; break;
        default: v0 = k; v1 = -i; v2 =  j; v3 =  r; break;
    }

    uint32_t h0, l0, h1, l1;
    split2(v0, v1, h0, l0);
    split2(v2, v3, h1, l1);
    size_t o = ((size_t)proj * DIM * DIM + (size_t)n * DIM + 4 * p) >> 2;
    ((uint2*)WhBase)[o] = make_uint2(h0, h1);
    ((uint2*)WlBase)[o] = make_uint2(l0, l1);
}

// ---------------- split fp32 activation into bf16 hi/lo --------------------
__global__ void split_kernel(const float* __restrict__ in,
                             __nv_bfloat16* __restrict__ hi,
                             __nv_bfloat16* __restrict__ lo) {
    int i = blockIdx.x * blockDim.x + threadIdx.x;     // float4 index
    float4 v = ((const float4*)in)[i];
    uint32_t h0, l0, h1, l1;
    split2(v.x, v.y, h0, l0);
    split2(v.z, v.w, h1, l1);
    ((uint2*)hi)[i] = make_uint2(h0, h1);
    ((uint2*)lo)[i] = make_uint2(l0, l1);
}

// ================= fused QKV projection GEMM ===============================
#define SMS   20
#define BUFU  10240
#define GEMM_SMEM (2 * BUFU * 4)

__device__ __forceinline__ void gemm_core(
    const __nv_bfloat16* pAh, const __nv_bfloat16* pAl,
    const __nv_bfloat16* pBh, const __nv_bfloat16* pBl,
    uint32_t sbase, uint32_t* smu, uint32_t doff0, uint32_t rstep,
    int wm, int wn, int g, int t, float acc[4][4][4]) {

    #define ISSUE_SLAB(s, b) do {                                              \
        int _k0 = (s) * 32;                                                    \
        uint32_t _d = sbase + (uint32_t)(b) * (BUFU * 4) + doff0;              \
        cp_async16(_d,                 pAh + _k0);                             \
        cp_async16(_d + rstep,         pAh + _k0 + (size_t)64 * DIM);          \
        cp_async16(_d + 2560*4,         pAl + _k0);                            \
        cp_async16(_d + 2560*4 + rstep, pAl + _k0 + (size_t)64 * DIM);         \
        cp_async16(_d + 5120*4,         pBh + _k0);                            \
        cp_async16(_d + 5120*4 + rstep, pBh + _k0 + (size_t)64 * DIM);         \
        cp_async16(_d + 7680*4,         pBl + _k0);                            \
        cp_async16(_d + 7680*4 + rstep, pBl + _k0 + (size_t)64 * DIM);         \
        CP_COMMIT();                                                           \
    } while (0)

    ISSUE_SLAB(0, 0);

    for (int s = 0; s < 32; s++) {
        const int cb = s & 1, nb = cb ^ 1;
        if (s + 1 < 32) {
            ISSUE_SLAB(s + 1, nb);
            CP_WAIT(1);
        } else {
            CP_WAIT(0);
        }
        __syncthreads();

        const uint32_t* base = smu + cb * BUFU;
        #pragma unroll
        for (int kk = 0; kk < 2; kk++) {
            uint32_t ah[4][4], al[4][4];
            #pragma unroll
            for (int mi = 0; mi < 4; mi++) {
                int r0 = (wm * 64 + mi * 16 + g) * SMS + kk * 8 + t;
                ah[mi][0] = base[r0];            ah[mi][1] = base[r0 + 8 * SMS];
                ah[mi][2] = base[r0 + 4];        ah[mi][3] = base[r0 + 8 * SMS + 4];
                al[mi][0] = base[2560 + r0];     al[mi][1] = base[2560 + r0 + 8 * SMS];
                al[mi][2] = base[2560 + r0 + 4]; al[mi][3] = base[2560 + r0 + 8 * SMS + 4];
            }
            uint32_t bh[4][2], bl[4][2];
            #pragma unroll
            for (int nj = 0; nj < 4; nj++) {
                int rn = (wn * 32 + nj * 8 + g) * SMS + kk * 8 + t;
                bh[nj][0] = base[5120 + rn]; bh[nj][1] = base[5120 + rn + 4];
                bl[nj][0] = base[7680 + rn]; bl[nj][1] = base[7680 + rn + 4];
            }
            #pragma unroll
            for (int mi = 0; mi < 4; mi++)
                #pragma unroll
                for (int nj = 0; nj < 4; nj++) {
                    mma16816(acc[mi][nj], ah[mi], bh[nj]);
                    mma16816(acc[mi][nj], ah[mi], bl[nj]);
                    mma16816(acc[mi][nj], al[mi], bh[nj]);
                }
        }
        __syncthreads();
    }
}

__global__ __launch_bounds__(256) void qkv_gemm(
    const __nv_bfloat16* __restrict__ Ah, const __nv_bfloat16* __restrict__ Al,
    const __nv_bfloat16* __restrict__ WhBase, const __nv_bfloat16* __restrict__ WlBase,
    const float* __restrict__ q_b, const float* __restrict__ k_b,
    const float* __restrict__ v_b,
    __nv_bfloat16* __restrict__ Qh, __nv_bfloat16* __restrict__ Ql,
    __nv_bfloat16* __restrict__ Kh, __nv_bfloat16* __restrict__ Kl,
    __nv_bfloat16* __restrict__ Vh, __nv_bfloat16* __restrict__ Vl) {
    extern __shared__ uint32_t smu[];
    const uint32_t sbase = smem_to_u32(smu);
    const int tid  = threadIdx.x;
    const int lane = tid & 31, wid = tid >> 5;
    const int g = lane >> 2, t = lane & 3;
    const int wm = wid & 1, wn = wid >> 1;
    const int bm = blockIdx.y * 128, bn = blockIdx.x * 128;
    const int z = blockIdx.z;

    const __nv_bfloat16* Bh = WhBase + (size_t)z * DIM * DIM;
    const __nv_bfloat16* Bl = WlBase + (size_t)z * DIM * DIM;
    const float* bias = (z == 0) ? q_b : (z == 1) ? k_b : v_b;
    __nv_bfloat16* Ch = (z == 0) ? Qh : (z == 1) ? Kh : Vh;
    __nv_bfloat16* Cl = (z == 0) ? Ql : (z == 1) ? Kl : Vl;

    float acc[4][4][4];
    #pragma unroll
    for (int i = 0; i < 4; i++)
        #pragma unroll
        for (int j = 0; j < 4; j++)
            #pragma unroll
            for (int q = 0; q < 4; q++) acc[i][j][q] = 0.f;

    const int crow0 = tid >> 2;
    const int ccol  = tid & 3;
    gemm_core(Ah + (size_t)(bm + crow0) * DIM + ccol * 8,
              Al + (size_t)(bm + crow0) * DIM + ccol * 8,
              Bh + (size_t)(bn + crow0) * DIM + ccol * 8,
              Bl + (size_t)(bn + crow0) * DIM + ccol * 8,
              sbase, smu,
              (uint32_t)(crow0 * SMS + ccol * 4) * 4,
              (uint32_t)(64 * SMS) * 4,
              wm, wn, g, t, acc);

    if (z == 2) {
        // ---- V: plain bf16 split ----
        #pragma unroll
        for (int mi = 0; mi < 4; mi++) {
            int row = bm + wm * 64 + mi * 16 + g;
            #pragma unroll
            for (int nj = 0; nj < 4; nj++) {
                int col = bn + wn * 32 + nj * 8 + 2 * t;
                float bx = bias[col], by = bias[col + 1];
                uint32_t h, l;
                split2(acc[mi][nj][0] + bx, acc[mi][nj][1] + by, h, l);
                *(uint32_t*)&Ch[(size_t)row * DIM + col] = h;
                *(uint32_t*)&Cl[(size_t)row * DIM + col] = l;
                split2(acc[mi][nj][2] + bx, acc[mi][nj][3] + by, h, l);
                *(uint32_t*)&Ch[(size_t)(row + 8) * DIM + col] = h;
                *(uint32_t*)&Cl[(size_t)(row + 8) * DIM + col] = l;
            }
        }
    } else {
        // ---- Q/K: fused RoPE + bf16 split; Q also folds softmax scale ----
        const bool evn = (t & 1) == 0;
        const float osc = (z == 0) ? QSCALE : 1.0f;
        #pragma unroll
        for (int nj = 0; nj < 4; nj++) {
            int col = bn + wn * 32 + nj * 8 + 2 * t;
            int grp = (col >> 2) & 15;
            float inv = powf(10000.0f, -(float)grp / 16.0f);
            int ax = grp % 3;
            float bx = bias[col], by = bias[col + 1];
            #pragma unroll
            for (int mi = 0; mi < 4; mi++) {
                int row = bm + wm * 64 + mi * 16 + g;
                float v0 = acc[mi][nj][0] + bx, v1 = acc[mi][nj][1] + by;
                float v2 = acc[mi][nj][2] + bx, v3 = acc[mi][nj][3] + by;
                float p0 = __shfl_xor_sync(0xFFFFFFFFu, v0, 1);
                float p1 = __shfl_xor_sync(0xFFFFFFFFu, v1, 1);
                float p2 = __shfl_xor_sync(0xFFFFFFFFu, v2, 1);
                float p3 = __shfl_xor_sync(0xFFFFFFFFu, v3, 1);
                #pragma unroll
                for (int half = 0; half < 2; half++) {
                    int r = row + 8 * half;
                    float a = (float)(r & 2047) * inv;
                    float cs = cosf(a), sn = sinf(a);
                    float a0 = half ? v2 : v0, a1 = half ? v3 : v1;
                    float b0 = half ? p2 : p0, b1 = half ? p3 : p1;
                    float xr, xi, xj, xk;
                    if (evn) { xr = a0; xi = a1; xj = b0; xk = b1; }
                    else     { xr = b0; xi = b1; xj = a0; xk = a1; }
                    float pr, pi, pj, pk;
                    qrot(cs, sn, ax, xr, xi, xj, xk, pr, pi, pj, pk);
                    float o0 = (evn ? pr : pj) * osc, o1 = (evn ? pi : pk) * osc;
                    uint32_t h, l;
                    split2(o0, o1, h, l);
                    *(uint32_t*)&Ch[(size_t)r * DIM + col] = h;
                    *(uint32_t*)&Cl[(size_t)r * DIM + col] = l;
                }
            }
        }
    }
}

// ================= O-projection GEMM (fp32 out) ============================
__global__ __launch_bounds__(256) void o_gemm(
    const __nv_bfloat16* __restrict__ Ah, const __nv_bfloat16* __restrict__ Al,
    const __nv_bfloat16* __restrict__ Bh, const __nv_bfloat16* __restrict__ Bl,
    const float* __restrict__ bias, float* __restrict__ C) {
    extern __shared__ uint32_t smu[];
    const uint32_t sbase = smem_to_u32(smu);
    const int tid  = threadIdx.x;
    const int lane = tid & 31, wid = tid >> 5;
    const int g = lane >> 2, t = lane & 3;
    const int wm = wid & 1, wn = wid >> 1;
    const int bm = blockIdx.y * 128, bn = blockIdx.x * 128;

    float acc[4][4][4];
    #pragma unroll
    for (int i = 0; i < 4; i++)
        #pragma unroll
        for (int j = 0; j < 4; j++)
            #pragma unroll
            for (int q = 0; q < 4; q++) acc[i][j][q] = 0.f;

    const int crow0 = tid >> 2;
    const int ccol  = tid & 3;
    gemm_core(Ah + (size_t)(bm + crow0) * DIM + ccol * 8,
              Al + (size_t)(bm + crow0) * DIM + ccol * 8,
              Bh + (size_t)(bn + crow0) * DIM + ccol * 8,
              Bl + (size_t)(bn + crow0) * DIM + ccol * 8,
              sbase, smu,
              (uint32_t)(crow0 * SMS + ccol * 4) * 4,
              (uint32_t)(64 * SMS) * 4,
              wm, wn, g, t, acc);

    #pragma unroll
    for (int mi = 0; mi < 4; mi++) {
        int row = bm + wm * 64 + mi * 16 + g;
        #pragma unroll
        for (int nj = 0; nj < 4; nj++) {
            int col = bn + wn * 32 + nj * 8 + 2 * t;
            float bx = bias[col], by = bias[col + 1];
            float2 v;
            v.x = acc[mi][nj][0] + bx; v.y = acc[mi][nj][1] + by;
            *(float2*)&C[(size_t)row * DIM + col] = v;
            v.x = acc[mi][nj][2] + bx; v.y = acc[mi][nj][3] + by;
            *(float2*)&C[(size_t)(row + 8) * DIM + col] = v;
        }
    }
}

// ================= tensor-core causal flash attention ======================
// 128q x 64k tiles, 8 warps, double-buffered K/V + persistent Q in smem.
// Q pre-scaled by 0.125*log2e -> softmax in log2 domain with raw ex2.
// smem: KV stage0 @0, stage1 @36864 (each Kh/Kl/Vh/Vl 9216B), Q @73728 (hi/lo).
#define ATT_STRIDE 144
#define ATT_STAGE  36864
#define ATT_QOFF   73728
#define ATT_SMEM   (ATT_QOFF + 36864)   /* 110592 */
__global__ __launch_bounds__(256, 2) void attn_tc(
    const __nv_bfloat16* __restrict__ Qh, const __nv_bfloat16* __restrict__ Ql,
    const __nv_bfloat16* __restrict__ Kh, const __nv_bfloat16* __restrict__ Kl,
    const __nv_bfloat16* __restrict__ Vh, const __nv_bfloat16* __restrict__ Vl,
    __nv_bfloat16* __restrict__ Oh, __nv_bfloat16* __restrict__ Ol) {
    extern __shared__ __align__(16) char sm[];
    const uint32_t sb = smem_to_u32(sm);
    const int tid = threadIdx.x, lane = tid & 31, wid = tid >> 5;
    const int g = lane >> 2, t = lane & 3;
    const int qt = (int)gridDim.x - 1 - (int)blockIdx.x;   // heavy blocks first
    const int bh = blockIdx.y;
    const int b = bh >> 4, h = bh & 15;
    const int qb = qt * 128;
    const size_t rbase = (size_t)b * SQ;
    const int hoff = h * DH;

    // ---- stage Q tile hi/lo into persistent smem region ----
    #pragma unroll
    for (int i = 0; i < 8; i++) {
        int half = i >> 2;
        int rem  = tid + 256 * (i & 3);       // 0..1023
        int r = rem >> 3, c = rem & 7;
        const __nv_bfloat16* src = (half ? Ql : Qh) + (rbase + qb + r) * DIM + hoff + c * 8;
        cp_async16(sb + ATT_QOFF + half * 18432 + r * ATT_STRIDE + c * 16, src);
    }
    CP_COMMIT();

    float Oa[8][4];
    #pragma unroll
    for (int j = 0; j < 8; j++)
        #pragma unroll
        for (int e = 0; e < 4; e++) Oa[j][e] = 0.f;
    float m0 = -1e30f, m1 = -1e30f, l0 = 0.f, l1 = 0.f;
    const int r0 = qb + wid * 16 + g;
    const int ntiles = 2 * qt + 2;

    const __nv_bfloat16* kv0 = Kh + rbase * DIM + hoff;
    const __nv_bfloat16* kv1 = Kl + rbase * DIM + hoff;
    const __nv_bfloat16* kv2 = Vh + rbase * DIM + hoff;
    const __nv_bfloat16* kv3 = Vl + rbase * DIM + hoff;

    #define ISSUE_KV(jt_, st_) do {                                             \
        int _kb = (jt_) * 64;                                                   \
        uint32_t _s = sb + (uint32_t)(st_) * ATT_STAGE;                         \
        _Pragma("unroll")                                                       \
        for (int i = 0; i < 8; i++) {                                           \
            int rem = (i & 1) ? tid + 256 : tid;                                \
            int r = rem >> 3, c = rem & 7;                                      \
            const __nv_bfloat16* src =                                          \
                (i >> 1) == 0 ? kv0 : (i >> 1) == 1 ? kv1 :                     \
                (i >> 1) == 2 ? kv2 : kv3;                                      \
            cp_async16(_s + (i >> 1) * 9216 + r * ATT_STRIDE + c * 16,          \
                       src + (size_t)(_kb + r) * DIM + c * 8);                  \
        }                                                                       \
        CP_COMMIT();                                                            \
    } while (0)

    ISSUE_KV(0, 0);

    const uint32_t qfbase = sb + ATT_QOFF + (wid * 16 + (lane & 15)) * ATT_STRIDE
                          + (lane >> 4) * 16;

    for (int jt = 0; jt < ntiles; jt++) {
        const int kb = jt * 64;
        const int cb = jt & 1, nb = cb ^ 1;
        if (jt + 1 < ntiles) {
            ISSUE_KV(jt + 1, nb);
            CP_WAIT(1);
        } else {
            CP_WAIT(0);
        }
        __syncthreads();
        const uint32_t stg = sb + (uint32_t)cb * ATT_STAGE;

        // ---- S = Q K^T (3-product split), Q fragments from smem ----
        float S[8][4];
        #pragma unroll
        for (int j = 0; j < 8; j++)
            #pragma unroll
            for (int e = 0; e < 4; e++) S[j][e] = 0.f;

        #pragma unroll
        for (int kc = 0; kc < 4; kc++) {
            uint32_t qfh[4], qfl[4];
            ldmatrix_x4(qfh, qfbase + kc * 32);
            ldmatrix_x4(qfl, qfbase + kc * 32 + 18432);
            uint32_t bkh[8][2], bkl[8][2];
            uint32_t kaddr = stg + (lane & 7) * ATT_STRIDE + kc * 32 + ((lane >> 3) & 1) * 16;
            #pragma unroll
            for (int j = 0; j < 8; j++) {
                ldmatrix_x2(bkh[j], kaddr + j * 8 * ATT_STRIDE);
                ldmatrix_x2(bkl[j], kaddr + j * 8 * ATT_STRIDE + 9216);
            }
            #pragma unroll
            for (int j = 0; j < 8; j++) {
                mma16816(S[j], qfh, bkh[j]);
                mma16816(S[j], qfh, bkl[j]);
                mma16816(S[j], qfl, bkh[j]);
            }
        }

        // ---- causal mask (S already scaled via Q) ----
        if (kb + 63 > qb) {
            #pragma unroll
            for (int j = 0; j < 8; j++) {
                int k0 = kb + 8 * j + 2 * t;
                if (k0     > r0    ) S[j][0] = -1e30f;
                if (k0 + 1 > r0    ) S[j][1] = -1e30f;
                if (k0     > r0 + 8) S[j][2] = -1e30f;
                if (k0 + 1 > r0 + 8) S[j][3] = -1e30f;
            }
        }

        // ---- online softmax (log2 domain) ----
        float tm0 = -1e30f, tm1 = -1e30f;
        #pragma unroll
        for (int j = 0; j < 8; j++) {
            tm0 = fmaxf(tm0, fmaxf(S[j][0], S[j][1]));
            tm1 = fmaxf(tm1, fmaxf(S[j][2], S[j][3]));
        }
        tm0 = fmaxf(tm0, __shfl_xor_sync(0xFFFFFFFFu, tm0, 1));
        tm0 = fmaxf(tm0, __shfl_xor_sync(0xFFFFFFFFu, tm0, 2));
        tm1 = fmaxf(tm1, __shfl_xor_sync(0xFFFFFFFFu, tm1, 1));
        tm1 = fmaxf(tm1, __shfl_xor_sync(0xFFFFFFFFu, tm1, 2));
        float mn0 = fmaxf(m0, tm0), mn1 = fmaxf(m1, tm1);
        float sc0 = ex2f(m0 - mn0), sc1 = ex2f(m1 - mn1);
        m0 = mn0; m1 = mn1;
        l0 *= sc0; l1 *= sc1;
        #pragma unroll
        for (int j = 0; j < 8; j++) {
            Oa[j][0] *= sc0; Oa[j][1] *= sc0;
            Oa[j][2] *= sc1; Oa[j][3] *= sc1;
        }
        #pragma unroll
        for (int j = 0; j < 8; j++) {
            S[j][0] = ex2f(S[j][0] - mn0); l0 += S[j][0];
            S[j][1] = ex2f(S[j][1] - mn0); l0 += S[j][1];
            S[j][2] = ex2f(S[j][2] - mn1); l1 += S[j][2];
            S[j][3] = ex2f(S[j][3] - mn1); l1 += S[j][3];
        }

        // ---- O += P V (3-product split) ----
        #pragma unroll
        for (int c = 0; c < 4; c++) {
            uint32_t pah[4], pal[4];
            split2(S[2*c  ][0], S[2*c  ][1], pah[0], pal[0]);
            split2(S[2*c  ][2], S[2*c  ][3], pah[1], pal[1]);
            split2(S[2*c+1][0], S[2*c+1][1], pah[2], pal[2]);
            split2(S[2*c+1][2], S[2*c+1][3], pah[3], pal[3]);
            uint32_t vaddr = stg + 18432 + (16 * c + (lane & 15)) * ATT_STRIDE;
            #pragma unroll
            for (int j = 0; j < 8; j++) {
                uint32_t bvh[2], bvl[2];
                ldmatrix_x2_trans(bvh, vaddr + j * 16);
                ldmatrix_x2_trans(bvl, vaddr + j * 16 + 9216);
                mma16816(Oa[j], pah, bvh);
                mma16816(Oa[j], pah, bvl);
                mma16816(Oa[j], pal, bvh);
            }
        }
        __syncthreads();
    }

    // ---- finalize: write bf16 hi/lo directly ----
    l0 += __shfl_xor_sync(0xFFFFFFFFu, l0, 1);
    l0 += __shfl_xor_sync(0xFFFFFFFFu, l0, 2);
    l1 += __shfl_xor_sync(0xFFFFFFFFu, l1, 1);
    l1 += __shfl_xor_sync(0xFFFFFFFFu, l1, 2);
    float inv0 = 1.f / l0, inv1 = 1.f / l1;
    size_t off0 = (rbase + r0) * DIM + hoff + 2 * t;
    size_t off1 = (rbase + r0 + 8) * DIM + hoff + 2 * t;
    #pragma unroll
    for (int j = 0; j < 8; j++) {
        uint32_t h, l;
        split2(Oa[j][0] * inv0, Oa[j][1] * inv0, h, l);
        *(uint32_t*)&Oh[off0 + 8 * j] = h;
        *(uint32_t*)&Ol[off0 + 8 * j] = l;
        split2(Oa[j][2] * inv1, Oa[j][3] * inv1, h, l);
        *(uint32_t*)&Oh[off1 + 8 * j] = h;
        *(uint32_t*)&Ol[off1 + 8 * j] = l;
    }
}

// ---------------- launch ---------------------------------------------------
extern "C" void kernel_launch(void* const* d_in, const int* in_sizes, int n_in,
                              void* d_out, int out_size) {
    const float* x = (const float*)d_in[0];
    // d_in[1] = mask (pure causal triu, ignored)
    const float* q_b = (const float*)d_in[6];
    const float* k_b = (const float*)d_in[11];
    const float* v_b = (const float*)d_in[16];
    const float* o_b = (const float*)d_in[21];

    WPtrs wp;
    for (int pr = 0; pr < 4; pr++)
        for (int cm = 0; cm < 4; cm++)
            wp.w[pr][cm] = (const float*)d_in[2 + 5 * pr + cm];

    __nv_bfloat16 *wh, *wl, *ah, *al, *qh, *ql, *kh, *kl, *vh, *vl;
    cudaGetSymbolAddress((void**)&wh, g_wh);
    cudaGetSymbolAddress((void**)&wl, g_wl);
    cudaGetSymbolAddress((void**)&ah, g_ah);
    cudaGetSymbolAddress((void**)&al, g_al);
    cudaGetSymbolAddress((void**)&qh, g_qh);
    cudaGetSymbolAddress((void**)&ql, g_ql);
    cudaGetSymbolAddress((void**)&kh, g_kh);
    cudaGetSymbolAddress((void**)&kl, g_kl);
    cudaGetSymbolAddress((void**)&vh, g_vh);
    cudaGetSymbolAddress((void**)&vl, g_vl);

    cudaFuncSetAttribute(qkv_gemm, cudaFuncAttributeMaxDynamicSharedMemorySize,
                         GEMM_SMEM);
    cudaFuncSetAttribute(o_gemm, cudaFuncAttributeMaxDynamicSharedMemorySize,
                         GEMM_SMEM);
    cudaFuncSetAttribute(attn_tc, cudaFuncAttributeMaxDynamicSharedMemorySize,
                         ATT_SMEM);

    dim3 wgrid((DIM * IQ) / 256, 4);
    build_w_all_kernel<<<wgrid, 256>>>(wp, wh, wl);

    const int sblocks = (MROW * DIM / 4) / 256;
    split_kernel<<<sblocks, 256>>>(x, ah, al);

    dim3 qkvgrid(DIM / 128, MROW / 128, 3);    // (8, 32, 3)
    qkv_gemm<<<qkvgrid, 256, GEMM_SMEM>>>(ah, al, wh, wl, q_b, k_b, v_b,
                                          qh, ql, kh, kl, vh, vl);

    dim3 agrid(SQ / 128, BQ * HQ);             // (16, 32)
    attn_tc<<<agrid, 256, ATT_SMEM>>>(qh, ql, kh, kl, vh, vl, ah, al);

    dim3 ogrid(DIM / 128, MROW / 128);         // (8, 32)
    o_gemm<<<ogrid, 256, GEMM_SMEM>>>(ah, al,
                                      wh + 3 * (size_t)DIM * DIM,
                                      wl + 3 * (size_t)DIM * DIM,
                                      o_b, (float*)d_out);
}

// round 10
// speedup vs baseline: 1.0159x; 1.0159x over previous
#include <cuda_runtime.h>
#include <cuda_bf16.h>
#include <math.h>
#include <cstdint>

#define BQ   2
#define SQ   2048
#define DIM  1024
#define HQ   16
#define DH   64
#define GQ   16
#define IQ   256
#define MROW (BQ*SQ)   /* 4096 */

// scores*0.125 folded into Q together with log2(e) so softmax uses raw ex2
#define QSCALE 0.18033688011112042f   /* 0.125 * log2(e) */

// ---------------- device scratch (no allocations allowed) ----------------
__device__ __nv_bfloat16 g_wh[4][DIM*DIM];   // W_eff hi, [n][k]
__device__ __nv_bfloat16 g_wl[4][DIM*DIM];   // W_eff lo
__device__ __nv_bfloat16 g_ah[MROW*DIM];     // activation hi (x, later attn out)
__device__ __nv_bfloat16 g_al[MROW*DIM];     // activation lo
__device__ __nv_bfloat16 g_qh[MROW*DIM];
__device__ __nv_bfloat16 g_ql[MROW*DIM];
__device__ __nv_bfloat16 g_kh[MROW*DIM];
__device__ __nv_bfloat16 g_kl[MROW*DIM];
__device__ __nv_bfloat16 g_vh[MROW*DIM];
__device__ __nv_bfloat16 g_vl[MROW*DIM];

// ---------------- helpers --------------------------------------------------
__device__ __forceinline__ uint32_t smem_to_u32(const void* p) {
    uint32_t a;
    asm("{ .reg .u64 t; cvta.to.shared.u64 t, %1; cvt.u32.u64 %0, t; }"
        : "=r"(a) : "l"(p));
    return a;
}
__device__ __forceinline__ void cp_async16(uint32_t dst, const void* src) {
    asm volatile("cp.async.ca.shared.global [%0], [%1], 16;"
                 :: "r"(dst), "l"(src));
}
#define CP_COMMIT() asm volatile("cp.async.commit_group;" ::: "memory")
#define CP_WAIT(n)  asm volatile("cp.async.wait_group %0;" :: "n"(n) : "memory")

__device__ __forceinline__ float ex2f(float x) {
    float r;
    asm("ex2.approx.f32 %0, %1;" : "=f"(r) : "f"(x));
    return r;
}

// split fp32 pair into bf16x2 hi (x low half, y high half) and lo
__device__ __forceinline__ void split2(float x, float y, uint32_t& hi, uint32_t& lo) {
    uint32_t h;
    asm("cvt.rn.bf16x2.f32 %0, %1, %2;" : "=r"(h) : "f"(y), "f"(x));
    float xh = __uint_as_float(h << 16);
    float yh = __uint_as_float(h & 0xFFFF0000u);
    float xl = x - xh, yl = y - yh;
    uint32_t l;
    asm("cvt.rn.bf16x2.f32 %0, %1, %2;" : "=r"(l) : "f"(yl), "f"(xl));
    hi = h; lo = l;
}

__device__ __forceinline__ void mma16816(float* c, const uint32_t* a, const uint32_t* b) {
    asm volatile(
        "mma.sync.aligned.m16n8k16.row.col.f32.bf16.bf16.f32 "
        "{%0,%1,%2,%3}, {%4,%5,%6,%7}, {%8,%9}, {%0,%1,%2,%3};"
        : "+f"(c[0]), "+f"(c[1]), "+f"(c[2]), "+f"(c[3])
        : "r"(a[0]), "r"(a[1]), "r"(a[2]), "r"(a[3]), "r"(b[0]), "r"(b[1]));
}
__device__ __forceinline__ void ldmatrix_x4(uint32_t* r, uint32_t addr) {
    asm volatile("ldmatrix.sync.aligned.m8n8.x4.shared.b16 {%0,%1,%2,%3}, [%4];"
                 : "=r"(r[0]), "=r"(r[1]), "=r"(r[2]), "=r"(r[3]) : "r"(addr));
}
__device__ __forceinline__ void ldmatrix_x2(uint32_t* r, uint32_t addr) {
    asm volatile("ldmatrix.sync.aligned.m8n8.x2.shared.b16 {%0,%1}, [%2];"
                 : "=r"(r[0]), "=r"(r[1]) : "r"(addr));
}
__device__ __forceinline__ void ldmatrix_x2_trans(uint32_t* r, uint32_t addr) {
    asm volatile("ldmatrix.sync.aligned.m8n8.x2.trans.shared.b16 {%0,%1}, [%2];"
                 : "=r"(r[0]), "=r"(r[1]) : "r"(addr));
}

// quaternion rope rotation (reference math, fp32)
__device__ __forceinline__ void qrot(float cs, float sn, int ax,
                                     float xr, float xi, float xj, float xk,
                                     float& pr, float& pi, float& pj, float& pk) {
    float ui = (ax == 0) ? sn : 0.f;
    float uj = (ax == 1) ? sn : 0.f;
    float uk = (ax == 2) ? sn : 0.f;
    pr = cs * xr - ui * xi - uj * xj - uk * xk;
    pi = cs * xi + ui * xr + uj * xk - uk * xj;
    pj = cs * xj - ui * xk + uj * xr + uk * xi;
    pk = cs * xk + ui * xj - uj * xi + uk * xr;
}

// ---------------- build all 4 effective quaternion weights -----------------
struct WPtrs { const float* w[4][4]; };   // [proj][comp r,i,j,k]
__global__ void build_w_all_kernel(WPtrs wp,
                                   __nv_bfloat16* __restrict__ WhBase,
                                   __nv_bfloat16* __restrict__ WlBase) {
    int proj = blockIdx.y;
    int idx = blockIdx.x * blockDim.x + threadIdx.x;   // 0 .. DIM*IQ-1
    int n = idx >> 8;          // 0..1023
    int p = idx & 255;         // 0..255
    int m = n >> 2, c = n & 3;

    int off = m * IQ + p;
    float r = wp.w[proj][0][off], i = wp.w[proj][1][off];
    float j = wp.w[proj][2][off], k = wp.w[proj][3][off];

    float v0, v1, v2, v3;
    switch (c) {
        case 0: v0 =  r; v1 = -i; v2 = -j; v3 = -k; break;
        case 1: v0 =  i; v1 =  r; v2 = -j; v3 =  k; break;
        case 2: v0 =  j; v1 =  i; v2 =  r; v3 = -k; break;
        default: v0 = k; v1 = -i; v2 =  j; v3 =  r; break;
    }

    uint32_t h0, l0, h1, l1;
    split2(v0, v1, h0, l0);
    split2(v2, v3, h1, l1);
    size_t o = ((size_t)proj * DIM * DIM + (size_t)n * DIM + 4 * p) >> 2;
    ((uint2*)WhBase)[o] = make_uint2(h0, h1);
    ((uint2*)WlBase)[o] = make_uint2(l0, l1);
}

// ---------------- split fp32 activation into bf16 hi/lo --------------------
__global__ void split_kernel(const float* __restrict__ in,
                             __nv_bfloat16* __restrict__ hi,
                             __nv_bfloat16* __restrict__ lo) {
    int i = blockIdx.x * blockDim.x + threadIdx.x;     // float4 index
    float4 v = ((const float4*)in)[i];
    uint32_t h0, l0, h1, l1;
    split2(v.x, v.y, h0, l0);
    split2(v.z, v.w, h1, l1);
    ((uint2*)hi)[i] = make_uint2(h0, h1);
    ((uint2*)lo)[i] = make_uint2(l0, l1);
}

// ================= fused QKV projection GEMM ===============================
#define SMS   20
#define BUFU  10240
#define GEMM_SMEM (2 * BUFU * 4)

__device__ __forceinline__ void gemm_core(
    const __nv_bfloat16* pAh, const __nv_bfloat16* pAl,
    const __nv_bfloat16* pBh, const __nv_bfloat16* pBl,
    uint32_t sbase, uint32_t* smu, uint32_t doff0, uint32_t rstep,
    int wm, int wn, int g, int t, float acc[4][4][4]) {

    #define ISSUE_SLAB(s, b) do {                                              \
        int _k0 = (s) * 32;                                                    \
        uint32_t _d = sbase + (uint32_t)(b) * (BUFU * 4) + doff0;              \
        cp_async16(_d,                 pAh + _k0);                             \
        cp_async16(_d + rstep,         pAh + _k0 + (size_t)64 * DIM);          \
        cp_async16(_d + 2560*4,         pAl + _k0);                            \
        cp_async16(_d + 2560*4 + rstep, pAl + _k0 + (size_t)64 * DIM);         \
        cp_async16(_d + 5120*4,         pBh + _k0);                            \
        cp_async16(_d + 5120*4 + rstep, pBh + _k0 + (size_t)64 * DIM);         \
        cp_async16(_d + 7680*4,         pBl + _k0);                            \
        cp_async16(_d + 7680*4 + rstep, pBl + _k0 + (size_t)64 * DIM);         \
        CP_COMMIT();                                                           \
    } while (0)

    ISSUE_SLAB(0, 0);

    for (int s = 0; s < 32; s++) {
        const int cb = s & 1, nb = cb ^ 1;
        if (s + 1 < 32) {
            ISSUE_SLAB(s + 1, nb);
            CP_WAIT(1);
        } else {
            CP_WAIT(0);
        }
        __syncthreads();

        const uint32_t* base = smu + cb * BUFU;
        #pragma unroll
        for (int kk = 0; kk < 2; kk++) {
            uint32_t ah[4][4], al[4][4];
            #pragma unroll
            for (int mi = 0; mi < 4; mi++) {
                int r0 = (wm * 64 + mi * 16 + g) * SMS + kk * 8 + t;
                ah[mi][0] = base[r0];            ah[mi][1] = base[r0 + 8 * SMS];
                ah[mi][2] = base[r0 + 4];        ah[mi][3] = base[r0 + 8 * SMS + 4];
                al[mi][0] = base[2560 + r0];     al[mi][1] = base[2560 + r0 + 8 * SMS];
                al[mi][2] = base[2560 + r0 + 4]; al[mi][3] = base[2560 + r0 + 8 * SMS + 4];
            }
            uint32_t bh[4][2], bl[4][2];
            #pragma unroll
            for (int nj = 0; nj < 4; nj++) {
                int rn = (wn * 32 + nj * 8 + g) * SMS + kk * 8 + t;
                bh[nj][0] = base[5120 + rn]; bh[nj][1] = base[5120 + rn + 4];
                bl[nj][0] = base[7680 + rn]; bl[nj][1] = base[7680 + rn + 4];
            }
            #pragma unroll
            for (int mi = 0; mi < 4; mi++)
                #pragma unroll
                for (int nj = 0; nj < 4; nj++) {
                    mma16816(acc[mi][nj], ah[mi], bh[nj]);
                    mma16816(acc[mi][nj], ah[mi], bl[nj]);
                    mma16816(acc[mi][nj], al[mi], bh[nj]);
                }
        }
        __syncthreads();
    }
}

__global__ __launch_bounds__(256) void qkv_gemm(
    const __nv_bfloat16* __restrict__ Ah, const __nv_bfloat16* __restrict__ Al,
    const __nv_bfloat16* __restrict__ WhBase, const __nv_bfloat16* __restrict__ WlBase,
    const float* __restrict__ q_b, const float* __restrict__ k_b,
    const float* __restrict__ v_b,
    __nv_bfloat16* __restrict__ Qh, __nv_bfloat16* __restrict__ Ql,
    __nv_bfloat16* __restrict__ Kh, __nv_bfloat16* __restrict__ Kl,
    __nv_bfloat16* __restrict__ Vh, __nv_bfloat16* __restrict__ Vl) {
    extern __shared__ uint32_t smu[];
    const uint32_t sbase = smem_to_u32(smu);
    const int tid  = threadIdx.x;
    const int lane = tid & 31, wid = tid >> 5;
    const int g = lane >> 2, t = lane & 3;
    const int wm = wid & 1, wn = wid >> 1;
    const int bm = blockIdx.y * 128, bn = blockIdx.x * 128;
    const int z = blockIdx.z;

    const __nv_bfloat16* Bh = WhBase + (size_t)z * DIM * DIM;
    const __nv_bfloat16* Bl = WlBase + (size_t)z * DIM * DIM;
    const float* bias = (z == 0) ? q_b : (z == 1) ? k_b : v_b;
    __nv_bfloat16* Ch = (z == 0) ? Qh : (z == 1) ? Kh : Vh;
    __nv_bfloat16* Cl = (z == 0) ? Ql : (z == 1) ? Kl : Vl;

    float acc[4][4][4];
    #pragma unroll
    for (int i = 0; i < 4; i++)
        #pragma unroll
        for (int j = 0; j < 4; j++)
            #pragma unroll
            for (int q = 0; q < 4; q++) acc[i][j][q] = 0.f;

    const int crow0 = tid >> 2;
    const int ccol  = tid & 3;
    gemm_core(Ah + (size_t)(bm + crow0) * DIM + ccol * 8,
              Al + (size_t)(bm + crow0) * DIM + ccol * 8,
              Bh + (size_t)(bn + crow0) * DIM + ccol * 8,
              Bl + (size_t)(bn + crow0) * DIM + ccol * 8,
              sbase, smu,
              (uint32_t)(crow0 * SMS + ccol * 4) * 4,
              (uint32_t)(64 * SMS) * 4,
              wm, wn, g, t, acc);

    if (z == 2) {
        // ---- V: plain bf16 split ----
        #pragma unroll
        for (int mi = 0; mi < 4; mi++) {
            int row = bm + wm * 64 + mi * 16 + g;
            #pragma unroll
            for (int nj = 0; nj < 4; nj++) {
                int col = bn + wn * 32 + nj * 8 + 2 * t;
                float bx = bias[col], by = bias[col + 1];
                uint32_t h, l;
                split2(acc[mi][nj][0] + bx, acc[mi][nj][1] + by, h, l);
                *(uint32_t*)&Ch[(size_t)row * DIM + col] = h;
                *(uint32_t*)&Cl[(size_t)row * DIM + col] = l;
                split2(acc[mi][nj][2] + bx, acc[mi][nj][3] + by, h, l);
                *(uint32_t*)&Ch[(size_t)(row + 8) * DIM + col] = h;
                *(uint32_t*)&Cl[(size_t)(row + 8) * DIM + col] = l;
            }
        }
    } else {
        // ---- Q/K: fused RoPE + bf16 split; Q also folds softmax scale ----
        const bool evn = (t & 1) == 0;
        const float osc = (z == 0) ? QSCALE : 1.0f;
        #pragma unroll
        for (int nj = 0; nj < 4; nj++) {
            int col = bn + wn * 32 + nj * 8 + 2 * t;
            int grp = (col >> 2) & 15;
            float inv = powf(10000.0f, -(float)grp / 16.0f);
            int ax = grp % 3;
            float bx = bias[col], by = bias[col + 1];
            #pragma unroll
            for (int mi = 0; mi < 4; mi++) {
                int row = bm + wm * 64 + mi * 16 + g;
                float v0 = acc[mi][nj][0] + bx, v1 = acc[mi][nj][1] + by;
                float v2 = acc[mi][nj][2] + bx, v3 = acc[mi][nj][3] + by;
                float p0 = __shfl_xor_sync(0xFFFFFFFFu, v0, 1);
                float p1 = __shfl_xor_sync(0xFFFFFFFFu, v1, 1);
                float p2 = __shfl_xor_sync(0xFFFFFFFFu, v2, 1);
                float p3 = __shfl_xor_sync(0xFFFFFFFFu, v3, 1);
                #pragma unroll
                for (int half = 0; half < 2; half++) {
                    int r = row + 8 * half;
                    float a = (float)(r & 2047) * inv;
                    float cs = cosf(a), sn = sinf(a);
                    float a0 = half ? v2 : v0, a1 = half ? v3 : v1;
                    float b0 = half ? p2 : p0, b1 = half ? p3 : p1;
                    float xr, xi, xj, xk;
                    if (evn) { xr = a0; xi = a1; xj = b0; xk = b1; }
                    else     { xr = b0; xi = b1; xj = a0; xk = a1; }
                    float pr, pi, pj, pk;
                    qrot(cs, sn, ax, xr, xi, xj, xk, pr, pi, pj, pk);
                    float o0 = (evn ? pr : pj) * osc, o1 = (evn ? pi : pk) * osc;
                    uint32_t h, l;
                    split2(o0, o1, h, l);
                    *(uint32_t*)&Ch[(size_t)r * DIM + col] = h;
                    *(uint32_t*)&Cl[(size_t)r * DIM + col] = l;
                }
            }
        }
    }
}

// ================= O-projection GEMM (fp32 out) ============================
__global__ __launch_bounds__(256) void o_gemm(
    const __nv_bfloat16* __restrict__ Ah, const __nv_bfloat16* __restrict__ Al,
    const __nv_bfloat16* __restrict__ Bh, const __nv_bfloat16* __restrict__ Bl,
    const float* __restrict__ bias, float* __restrict__ C) {
    extern __shared__ uint32_t smu[];
    const uint32_t sbase = smem_to_u32(smu);
    const int tid  = threadIdx.x;
    const int lane = tid & 31, wid = tid >> 5;
    const int g = lane >> 2, t = lane & 3;
    const int wm = wid & 1, wn = wid >> 1;
    const int bm = blockIdx.y * 128, bn = blockIdx.x * 128;

    float acc[4][4][4];
    #pragma unroll
    for (int i = 0; i < 4; i++)
        #pragma unroll
        for (int j = 0; j < 4; j++)
            #pragma unroll
            for (int q = 0; q < 4; q++) acc[i][j][q] = 0.f;

    const int crow0 = tid >> 2;
    const int ccol  = tid & 3;
    gemm_core(Ah + (size_t)(bm + crow0) * DIM + ccol * 8,
              Al + (size_t)(bm + crow0) * DIM + ccol * 8,
              Bh + (size_t)(bn + crow0) * DIM + ccol * 8,
              Bl + (size_t)(bn + crow0) * DIM + ccol * 8,
              sbase, smu,
              (uint32_t)(crow0 * SMS + ccol * 4) * 4,
              (uint32_t)(64 * SMS) * 4,
              wm, wn, g, t, acc);

    #pragma unroll
    for (int mi = 0; mi < 4; mi++) {
        int row = bm + wm * 64 + mi * 16 + g;
        #pragma unroll
        for (int nj = 0; nj < 4; nj++) {
            int col = bn + wn * 32 + nj * 8 + 2 * t;
            float bx = bias[col], by = bias[col + 1];
            float2 v;
            v.x = acc[mi][nj][0] + bx; v.y = acc[mi][nj][1] + by;
            *(float2*)&C[(size_t)row * DIM + col] = v;
            v.x = acc[mi][nj][2] + bx; v.y = acc[mi][nj][3] + by;
            *(float2*)&C[(size_t)(row + 8) * DIM + col] = v;
        }
    }
}

// ================= tensor-core causal flash attention ======================
// 128q x 64k tiles, 8 warps, Q in registers, double-buffered K/V (72KB),
// 2 CTAs/SM. Q staged through stage0 region then overwritten by K/V.
// K/V fragments loaded per-j inside MMA loops to minimize live registers.
#define ATT_STRIDE 144
#define ATT_STAGE  36864
#define ATT_SMEM   (2 * ATT_STAGE)      /* 73728 */
__global__ __launch_bounds__(256, 2) void attn_tc(
    const __nv_bfloat16* __restrict__ Qh, const __nv_bfloat16* __restrict__ Ql,
    const __nv_bfloat16* __restrict__ Kh, const __nv_bfloat16* __restrict__ Kl,
    const __nv_bfloat16* __restrict__ Vh, const __nv_bfloat16* __restrict__ Vl,
    __nv_bfloat16* __restrict__ Oh, __nv_bfloat16* __restrict__ Ol) {
    extern __shared__ __align__(16) char sm[];
    const uint32_t sb = smem_to_u32(sm);
    const int tid = threadIdx.x, lane = tid & 31, wid = tid >> 5;
    const int g = lane >> 2, t = lane & 3;
    const int qt = (int)gridDim.x - 1 - (int)blockIdx.x;   // heavy blocks first
    const int bh = blockIdx.y;
    const int b = bh >> 4, h = bh & 15;
    const int qb = qt * 128;
    const size_t rbase = (size_t)b * SQ;
    const int hoff = h * DH;

    // ---- stage Q tile hi/lo into stage0+stage1 region, extract to regs ----
    #pragma unroll
    for (int i = 0; i < 8; i++) {
        int half = i >> 2;
        int rem  = tid + 256 * (i & 3);       // 0..1023
        int r = rem >> 3, c = rem & 7;
        const __nv_bfloat16* src = (half ? Ql : Qh) + (rbase + qb + r) * DIM + hoff + c * 8;
        cp_async16(sb + half * 18432 + r * ATT_STRIDE + c * 16, src);
    }
    CP_COMMIT(); CP_WAIT(0);
    __syncthreads();

    uint32_t qfh[4][4], qfl[4][4];
    {
        uint32_t abase = sb + (wid * 16 + (lane & 15)) * ATT_STRIDE + (lane >> 4) * 16;
        #pragma unroll
        for (int kc = 0; kc < 4; kc++) {
            ldmatrix_x4(qfh[kc], abase + kc * 32);
            ldmatrix_x4(qfl[kc], abase + kc * 32 + 18432);
        }
    }
    __syncthreads();

    float Oa[8][4];
    #pragma unroll
    for (int j = 0; j < 8; j++)
        #pragma unroll
        for (int e = 0; e < 4; e++) Oa[j][e] = 0.f;
    float m0 = -1e30f, m1 = -1e30f, l0 = 0.f, l1 = 0.f;
    const int r0 = qb + wid * 16 + g;
    const int ntiles = 2 * qt + 2;

    const __nv_bfloat16* kv0 = Kh + rbase * DIM + hoff;
    const __nv_bfloat16* kv1 = Kl + rbase * DIM + hoff;
    const __nv_bfloat16* kv2 = Vh + rbase * DIM + hoff;
    const __nv_bfloat16* kv3 = Vl + rbase * DIM + hoff;

    #define ISSUE_KV(jt_, st_) do {                                             \
        int _kb = (jt_) * 64;                                                   \
        uint32_t _s = sb + (uint32_t)(st_) * ATT_STAGE;                         \
        _Pragma("unroll")                                                       \
        for (int i = 0; i < 8; i++) {                                           \
            int rem = (i & 1) ? tid + 256 : tid;                                \
            int r = rem >> 3, c = rem & 7;                                      \
            const __nv_bfloat16* src =                                          \
                (i >> 1) == 0 ? kv0 : (i >> 1) == 1 ? kv1 :                     \
                (i >> 1) == 2 ? kv2 : kv3;                                      \
            cp_async16(_s + (i >> 1) * 9216 + r * ATT_STRIDE + c * 16,          \
                       src + (size_t)(_kb + r) * DIM + c * 8);                  \
        }                                                                       \
        CP_COMMIT();                                                            \
    } while (0)

    ISSUE_KV(0, 0);

    for (int jt = 0; jt < ntiles; jt++) {
        const int kb = jt * 64;
        const int cb = jt & 1, nb = cb ^ 1;
        if (jt + 1 < ntiles) {
            ISSUE_KV(jt + 1, nb);
            CP_WAIT(1);
        } else {
            CP_WAIT(0);
        }
        __syncthreads();
        const uint32_t stg = sb + (uint32_t)cb * ATT_STAGE;

        // ---- S = Q K^T (3-product split), K fragments loaded per-j ----
        float S[8][4];
        #pragma unroll
        for (int j = 0; j < 8; j++)
            #pragma unroll
            for (int e = 0; e < 4; e++) S[j][e] = 0.f;

        #pragma unroll
        for (int kc = 0; kc < 4; kc++) {
            uint32_t kaddr = stg + (lane & 7) * ATT_STRIDE + kc * 32 + ((lane >> 3) & 1) * 16;
            #pragma unroll
            for (int j = 0; j < 8; j++) {
                uint32_t bkh[2], bkl[2];
                ldmatrix_x2(bkh, kaddr + j * 8 * ATT_STRIDE);
                ldmatrix_x2(bkl, kaddr + j * 8 * ATT_STRIDE + 9216);
                mma16816(S[j], qfh[kc], bkh);
                mma16816(S[j], qfh[kc], bkl);
                mma16816(S[j], qfl[kc], bkh);
            }
        }

        // ---- causal mask (S already scaled via Q) ----
        if (kb + 63 > qb) {
            #pragma unroll
            for (int j = 0; j < 8; j++) {
                int k0 = kb + 8 * j + 2 * t;
                if (k0     > r0    ) S[j][0] = -1e30f;
                if (k0 + 1 > r0    ) S[j][1] = -1e30f;
                if (k0     > r0 + 8) S[j][2] = -1e30f;
                if (k0 + 1 > r0 + 8) S[j][3] = -1e30f;
            }
        }

        // ---- online softmax (log2 domain) ----
        float tm0 = -1e30f, tm1 = -1e30f;
        #pragma unroll
        for (int j = 0; j < 8; j++) {
            tm0 = fmaxf(tm0, fmaxf(S[j][0], S[j][1]));
            tm1 = fmaxf(tm1, fmaxf(S[j][2], S[j][3]));
        }
        tm0 = fmaxf(tm0, __shfl_xor_sync(0xFFFFFFFFu, tm0, 1));
        tm0 = fmaxf(tm0, __shfl_xor_sync(0xFFFFFFFFu, tm0, 2));
        tm1 = fmaxf(tm1, __shfl_xor_sync(0xFFFFFFFFu, tm1, 1));
        tm1 = fmaxf(tm1, __shfl_xor_sync(0xFFFFFFFFu, tm1, 2));
        float mn0 = fmaxf(m0, tm0), mn1 = fmaxf(m1, tm1);
        float sc0 = ex2f(m0 - mn0), sc1 = ex2f(m1 - mn1);
        m0 = mn0; m1 = mn1;
        l0 *= sc0; l1 *= sc1;
        #pragma unroll
        for (int j = 0; j < 8; j++) {
            Oa[j][0] *= sc0; Oa[j][1] *= sc0;
            Oa[j][2] *= sc1; Oa[j][3] *= sc1;
        }
        #pragma unroll
        for (int j = 0; j < 8; j++) {
            S[j][0] = ex2f(S[j][0] - mn0); l0 += S[j][0];
            S[j][1] = ex2f(S[j][1] - mn0); l0 += S[j][1];
            S[j][2] = ex2f(S[j][2] - mn1); l1 += S[j][2];
            S[j][3] = ex2f(S[j][3] - mn1); l1 += S[j][3];
        }

        // ---- O += P V (3-product split), V fragments loaded per-j ----
        #pragma unroll
        for (int c = 0; c < 4; c++) {
            uint32_t pah[4], pal[4];
            split2(S[2*c  ][0], S[2*c  ][1], pah[0], pal[0]);
            split2(S[2*c  ][2], S[2*c  ][3], pah[1], pal[1]);
            split2(S[2*c+1][0], S[2*c+1][1], pah[2], pal[2]);
            split2(S[2*c+1][2], S[2*c+1][3], pah[3], pal[3]);
            uint32_t vaddr = stg + 18432 + (16 * c + (lane & 15)) * ATT_STRIDE;
            #pragma unroll
            for (int j = 0; j < 8; j++) {
                uint32_t bvh[2], bvl[2];
                ldmatrix_x2_trans(bvh, vaddr + j * 16);
                ldmatrix_x2_trans(bvl, vaddr + j * 16 + 9216);
                mma16816(Oa[j], pah, bvh);
                mma16816(Oa[j], pah, bvl);
                mma16816(Oa[j], pal, bvh);
            }
        }
        __syncthreads();
    }

    // ---- finalize: write bf16 hi/lo directly ----
    l0 += __shfl_xor_sync(0xFFFFFFFFu, l0, 1);
    l0 += __shfl_xor_sync(0xFFFFFFFFu, l0, 2);
    l1 += __shfl_xor_sync(0xFFFFFFFFu, l1, 1);
    l1 += __shfl_xor_sync(0xFFFFFFFFu, l1, 2);
    float inv0 = 1.f / l0, inv1 = 1.f / l1;
    size_t off0 = (rbase + r0) * DIM + hoff + 2 * t;
    size_t off1 = (rbase + r0 + 8) * DIM + hoff + 2 * t;
    #pragma unroll
    for (int j = 0; j < 8; j++) {
        uint32_t h, l;
        split2(Oa[j][0] * inv0, Oa[j][1] * inv0, h, l);
        *(uint32_t*)&Oh[off0 + 8 * j] = h;
        *(uint32_t*)&Ol[off0 + 8 * j] = l;
        split2(Oa[j][2] * inv1, Oa[j][3] * inv1, h, l);
        *(uint32_t*)&Oh[off1 + 8 * j] = h;
        *(uint32_t*)&Ol[off1 + 8 * j] = l;
    }
}

// ---------------- launch ---------------------------------------------------
extern "C" void kernel_launch(void* const* d_in, const int* in_sizes, int n_in,
                              void* d_out, int out_size) {
    const float* x = (const float*)d_in[0];
    // d_in[1] = mask (pure causal triu, ignored)
    const float* q_b = (const float*)d_in[6];
    const float* k_b = (const float*)d_in[11];
    const float* v_b = (const float*)d_in[16];
    const float* o_b = (const float*)d_in[21];

    WPtrs wp;
    for (int pr = 0; pr < 4; pr++)
        for (int cm = 0; cm < 4; cm++)
            wp.w[pr][cm] = (const float*)d_in[2 + 5 * pr + cm];

    __nv_bfloat16 *wh, *wl, *ah, *al, *qh, *ql, *kh, *kl, *vh, *vl;
    cudaGetSymbolAddress((void**)&wh, g_wh);
    cudaGetSymbolAddress((void**)&wl, g_wl);
    cudaGetSymbolAddress((void**)&ah, g_ah);
    cudaGetSymbolAddress((void**)&al, g_al);
    cudaGetSymbolAddress((void**)&qh, g_qh);
    cudaGetSymbolAddress((void**)&ql, g_ql);
    cudaGetSymbolAddress((void**)&kh, g_kh);
    cudaGetSymbolAddress((void**)&kl, g_kl);
    cudaGetSymbolAddress((void**)&vh, g_vh);
    cudaGetSymbolAddress((void**)&vl, g_vl);

    cudaFuncSetAttribute(qkv_gemm, cudaFuncAttributeMaxDynamicSharedMemorySize,
                         GEMM_SMEM);
    cudaFuncSetAttribute(o_gemm, cudaFuncAttributeMaxDynamicSharedMemorySize,
                         GEMM_SMEM);
    cudaFuncSetAttribute(attn_tc, cudaFuncAttributeMaxDynamicSharedMemorySize,
                         ATT_SMEM);

    dim3 wgrid((DIM * IQ) / 256, 4);
    build_w_all_kernel<<<wgrid, 256>>>(wp, wh, wl);

    const int sblocks = (MROW * DIM / 4) / 256;
    split_kernel<<<sblocks, 256>>>(x, ah, al);

    dim3 qkvgrid(DIM / 128, MROW / 128, 3);    // (8, 32, 3)
    qkv_gemm<<<qkvgrid, 256, GEMM_SMEM>>>(ah, al, wh, wl, q_b, k_b, v_b,
                                          qh, ql, kh, kl, vh, vl);

    dim3 agrid(SQ / 128, BQ * HQ);             // (16, 32)
    attn_tc<<<agrid, 256, ATT_SMEM>>>(qh, ql, kh, kl, vh, vl, ah, al);

    dim3 ogrid(DIM / 128, MROW / 128);         // (8, 32)
    o_gemm<<<ogrid, 256, GEMM_SMEM>>>(ah, al,
                                      wh + 3 * (size_t)DIM * DIM,
                                      wl + 3 * (size_t)DIM * DIM,
                                      o_b, (float*)d_out);
}

// round 11
// speedup vs baseline: 1.4155x; 1.3933x over previous
#include <cuda_runtime.h>
#include <cuda_fp16.h>
#include <math.h>
#include <cstdint>

#define BQ   2
#define SQ   2048
#define DIM  1024
#define HQ   16
#define DH   64
#define GQ   16
#define IQ   256
#define MROW (BQ*SQ)   /* 4096 */

// scores*0.125 folded into Q together with log2(e) so softmax uses raw ex2
#define QSCALE 0.18033688011112042f   /* 0.125 * log2(e) */

// ---------------- device scratch (no allocations allowed) ----------------
__device__ __half g_wh[4][DIM*DIM];   // W_eff hi, [n][k]
__device__ __half g_wl[4][DIM*DIM];   // W_eff lo (residual)
__device__ __half g_a1[MROW*DIM];     // activation, single fp16 (x / attn out)
__device__ __half g_q1[MROW*DIM];     // Q single fp16 (rope+scale applied)
__device__ __half g_kh[MROW*DIM];
__device__ __half g_kl[MROW*DIM];
__device__ __half g_vh[MROW*DIM];
__device__ __half g_vl[MROW*DIM];

// ---------------- helpers --------------------------------------------------
__device__ __forceinline__ uint32_t smem_to_u32(const void* p) {
    uint32_t a;
    asm("{ .reg .u64 t; cvta.to.shared.u64 t, %1; cvt.u32.u64 %0, t; }"
        : "=r"(a) : "l"(p));
    return a;
}
__device__ __forceinline__ void cp_async16(uint32_t dst, const void* src) {
    asm volatile("cp.async.ca.shared.global [%0], [%1], 16;"
                 :: "r"(dst), "l"(src));
}
#define CP_COMMIT() asm volatile("cp.async.commit_group;" ::: "memory")
#define CP_WAIT(n)  asm volatile("cp.async.wait_group %0;" :: "n"(n) : "memory")

__device__ __forceinline__ float ex2f(float x) {
    float r;
    asm("ex2.approx.f32 %0, %1;" : "=f"(r) : "f"(x));
    return r;
}

// pack two fp32 into f16x2 (x in low half)
__device__ __forceinline__ uint32_t packf16(float x, float y) {
    __half2 h = __floats2half2_rn(x, y);
    return *reinterpret_cast<uint32_t*>(&h);
}
// split fp32 pair into f16x2 hi and f16x2 lo (residual)
__device__ __forceinline__ void splitf16(float x, float y, uint32_t& hi, uint32_t& lo) {
    __half2 h2 = __floats2half2_rn(x, y);
    hi = *reinterpret_cast<uint32_t*>(&h2);
    float xh = __half2float(__low2half(h2));
    float yh = __half2float(__high2half(h2));
    __half2 l2 = __floats2half2_rn(x - xh, y - yh);
    lo = *reinterpret_cast<uint32_t*>(&l2);
}

__device__ __forceinline__ void mma16816h(float* c, const uint32_t* a, const uint32_t* b) {
    asm volatile(
        "mma.sync.aligned.m16n8k16.row.col.f32.f16.f16.f32 "
        "{%0,%1,%2,%3}, {%4,%5,%6,%7}, {%8,%9}, {%0,%1,%2,%3};"
        : "+f"(c[0]), "+f"(c[1]), "+f"(c[2]), "+f"(c[3])
        : "r"(a[0]), "r"(a[1]), "r"(a[2]), "r"(a[3]), "r"(b[0]), "r"(b[1]));
}
__device__ __forceinline__ void ldmatrix_x4(uint32_t* r, uint32_t addr) {
    asm volatile("ldmatrix.sync.aligned.m8n8.x4.shared.b16 {%0,%1,%2,%3}, [%4];"
                 : "=r"(r[0]), "=r"(r[1]), "=r"(r[2]), "=r"(r[3]) : "r"(addr));
}
__device__ __forceinline__ void ldmatrix_x2(uint32_t* r, uint32_t addr) {
    asm volatile("ldmatrix.sync.aligned.m8n8.x2.shared.b16 {%0,%1}, [%2];"
                 : "=r"(r[0]), "=r"(r[1]) : "r"(addr));
}
__device__ __forceinline__ void ldmatrix_x2_trans(uint32_t* r, uint32_t addr) {
    asm volatile("ldmatrix.sync.aligned.m8n8.x2.trans.shared.b16 {%0,%1}, [%2];"
                 : "=r"(r[0]), "=r"(r[1]) : "r"(addr));
}

// quaternion rope rotation (reference math, fp32)
__device__ __forceinline__ void qrot(float cs, float sn, int ax,
                                     float xr, float xi, float xj, float xk,
                                     float& pr, float& pi, float& pj, float& pk) {
    float ui = (ax == 0) ? sn : 0.f;
    float uj = (ax == 1) ? sn : 0.f;
    float uk = (ax == 2) ? sn : 0.f;
    pr = cs * xr - ui * xi - uj * xj - uk * xk;
    pi = cs * xi + ui * xr + uj * xk - uk * xj;
    pj = cs * xj - ui * xk + uj * xr + uk * xi;
    pk = cs * xk + ui * xj - uj * xi + uk * xr;
}

// ---------------- build all 4 effective quaternion weights (fp16 hi/lo) ----
struct WPtrs { const float* w[4][4]; };   // [proj][comp r,i,j,k]
__global__ void build_w_all_kernel(WPtrs wp,
                                   __half* __restrict__ WhBase,
                                   __half* __restrict__ WlBase) {
    int proj = blockIdx.y;
    int idx = blockIdx.x * blockDim.x + threadIdx.x;   // 0 .. DIM*IQ-1
    int n = idx >> 8;          // 0..1023
    int p = idx & 255;         // 0..255
    int m = n >> 2, c = n & 3;

    int off = m * IQ + p;
    float r = wp.w[proj][0][off], i = wp.w[proj][1][off];
    float j = wp.w[proj][2][off], k = wp.w[proj][3][off];

    float v0, v1, v2, v3;
    switch (c) {
        case 0: v0 =  r; v1 = -i; v2 = -j; v3 = -k; break;
        case 1: v0 =  i; v1 =  r; v2 = -j; v3 =  k; break;
        case 2: v0 =  j; v1 =  i; v2 =  r; v3 = -k; break;
        default: v0 = k; v1 = -i; v2 =  j; v3 =  r; break;
    }

    uint32_t h0, l0, h1, l1;
    splitf16(v0, v1, h0, l0);
    splitf16(v2, v3, h1, l1);
    size_t o = ((size_t)proj * DIM * DIM + (size_t)n * DIM + 4 * p) >> 2;
    ((uint2*)WhBase)[o] = make_uint2(h0, h1);
    ((uint2*)WlBase)[o] = make_uint2(l0, l1);
}

// ---------------- convert fp32 activation into single fp16 -----------------
__global__ void cvt16_kernel(const float* __restrict__ in,
                             __half* __restrict__ out) {
    int i = blockIdx.x * blockDim.x + threadIdx.x;     // float4 index
    float4 v = ((const float4*)in)[i];
    ((uint2*)out)[i] = make_uint2(packf16(v.x, v.y), packf16(v.z, v.w));
}

// ================= fp16 2-product GEMM core ================================
// C = A_fp16 @ (Bh + Bl)^T : A single fp16, B split hi/lo.
// Tile 128x128, 8 warps, K-slab 32, double buffered.
// smem per buffer (u32): A@0, Bh@2560, Bl@5120; row stride 20 u32.
#define SMS   20
#define BUFU  7680
#define GEMM_SMEM (2 * BUFU * 4)   /* 61440 */

__device__ __forceinline__ void gemm_core(
    const __half* pA, const __half* pBh, const __half* pBl,
    uint32_t sbase, uint32_t* smu, uint32_t doff0, uint32_t rstep,
    int wm, int wn, int g, int t, float acc[4][4][4]) {

    #define ISSUE_SLAB(s, b) do {                                              \
        int _k0 = (s) * 32;                                                    \
        uint32_t _d = sbase + (uint32_t)(b) * (BUFU * 4) + doff0;              \
        cp_async16(_d,                  pA  + _k0);                            \
        cp_async16(_d + rstep,          pA  + _k0 + (size_t)64 * DIM);         \
        cp_async16(_d + 2560*4,         pBh + _k0);                            \
        cp_async16(_d + 2560*4 + rstep, pBh + _k0 + (size_t)64 * DIM);         \
        cp_async16(_d + 5120*4,         pBl + _k0);                            \
        cp_async16(_d + 5120*4 + rstep, pBl + _k0 + (size_t)64 * DIM);         \
        CP_COMMIT();                                                           \
    } while (0)

    ISSUE_SLAB(0, 0);

    for (int s = 0; s < 32; s++) {
        const int cb = s & 1, nb = cb ^ 1;
        if (s + 1 < 32) {
            ISSUE_SLAB(s + 1, nb);
            CP_WAIT(1);
        } else {
            CP_WAIT(0);
        }
        __syncthreads();

        const uint32_t* base = smu + cb * BUFU;
        #pragma unroll
        for (int kk = 0; kk < 2; kk++) {
            uint32_t a[4][4];
            #pragma unroll
            for (int mi = 0; mi < 4; mi++) {
                int r0 = (wm * 64 + mi * 16 + g) * SMS + kk * 8 + t;
                a[mi][0] = base[r0];     a[mi][1] = base[r0 + 8 * SMS];
                a[mi][2] = base[r0 + 4]; a[mi][3] = base[r0 + 8 * SMS + 4];
            }
            uint32_t bh[4][2], bl[4][2];
            #pragma unroll
            for (int nj = 0; nj < 4; nj++) {
                int rn = (wn * 32 + nj * 8 + g) * SMS + kk * 8 + t;
                bh[nj][0] = base[2560 + rn]; bh[nj][1] = base[2560 + rn + 4];
                bl[nj][0] = base[5120 + rn]; bl[nj][1] = base[5120 + rn + 4];
            }
            #pragma unroll
            for (int mi = 0; mi < 4; mi++)
                #pragma unroll
                for (int nj = 0; nj < 4; nj++) {
                    mma16816h(acc[mi][nj], a[mi], bh[nj]);
                    mma16816h(acc[mi][nj], a[mi], bl[nj]);
                }
        }
        __syncthreads();
    }
}

// z = 0: Q (rope + scale, single fp16 out); 1: K (rope, hi/lo out);
// 2: V (hi/lo out).
__global__ __launch_bounds__(256) void qkv_gemm(
    const __half* __restrict__ A1,
    const __half* __restrict__ WhBase, const __half* __restrict__ WlBase,
    const float* __restrict__ q_b, const float* __restrict__ k_b,
    const float* __restrict__ v_b,
    __half* __restrict__ Q1,
    __half* __restrict__ Kh, __half* __restrict__ Kl,
    __half* __restrict__ Vh, __half* __restrict__ Vl) {
    extern __shared__ uint32_t smu[];
    const uint32_t sbase = smem_to_u32(smu);
    const int tid  = threadIdx.x;
    const int lane = tid & 31, wid = tid >> 5;
    const int g = lane >> 2, t = lane & 3;
    const int wm = wid & 1, wn = wid >> 1;
    const int bm = blockIdx.y * 128, bn = blockIdx.x * 128;
    const int z = blockIdx.z;

    const __half* Bh = WhBase + (size_t)z * DIM * DIM;
    const __half* Bl = WlBase + (size_t)z * DIM * DIM;
    const float* bias = (z == 0) ? q_b : (z == 1) ? k_b : v_b;

    float acc[4][4][4];
    #pragma unroll
    for (int i = 0; i < 4; i++)
        #pragma unroll
        for (int j = 0; j < 4; j++)
            #pragma unroll
            for (int q = 0; q < 4; q++) acc[i][j][q] = 0.f;

    const int crow0 = tid >> 2;
    const int ccol  = tid & 3;
    gemm_core(A1 + (size_t)(bm + crow0) * DIM + ccol * 8,
              Bh + (size_t)(bn + crow0) * DIM + ccol * 8,
              Bl + (size_t)(bn + crow0) * DIM + ccol * 8,
              sbase, smu,
              (uint32_t)(crow0 * SMS + ccol * 4) * 4,
              (uint32_t)(64 * SMS) * 4,
              wm, wn, g, t, acc);

    if (z == 2) {
        // ---- V: fp16 hi/lo split ----
        #pragma unroll
        for (int mi = 0; mi < 4; mi++) {
            int row = bm + wm * 64 + mi * 16 + g;
            #pragma unroll
            for (int nj = 0; nj < 4; nj++) {
                int col = bn + wn * 32 + nj * 8 + 2 * t;
                float bx = bias[col], by = bias[col + 1];
                uint32_t h, l;
                splitf16(acc[mi][nj][0] + bx, acc[mi][nj][1] + by, h, l);
                *(uint32_t*)&Vh[(size_t)row * DIM + col] = h;
                *(uint32_t*)&Vl[(size_t)row * DIM + col] = l;
                splitf16(acc[mi][nj][2] + bx, acc[mi][nj][3] + by, h, l);
                *(uint32_t*)&Vh[(size_t)(row + 8) * DIM + col] = h;
                *(uint32_t*)&Vl[(size_t)(row + 8) * DIM + col] = l;
            }
        }
    } else {
        // ---- Q/K: fused RoPE; Q single fp16 (+scale), K fp16 hi/lo ----
        const bool evn = (t & 1) == 0;
        #pragma unroll
        for (int nj = 0; nj < 4; nj++) {
            int col = bn + wn * 32 + nj * 8 + 2 * t;
            int grp = (col >> 2) & 15;
            float inv = powf(10000.0f, -(float)grp / 16.0f);
            int ax = grp % 3;
            float bx = bias[col], by = bias[col + 1];
            #pragma unroll
            for (int mi = 0; mi < 4; mi++) {
                int row = bm + wm * 64 + mi * 16 + g;
                float v0 = acc[mi][nj][0] + bx, v1 = acc[mi][nj][1] + by;
                float v2 = acc[mi][nj][2] + bx, v3 = acc[mi][nj][3] + by;
                float p0 = __shfl_xor_sync(0xFFFFFFFFu, v0, 1);
                float p1 = __shfl_xor_sync(0xFFFFFFFFu, v1, 1);
                float p2 = __shfl_xor_sync(0xFFFFFFFFu, v2, 1);
                float p3 = __shfl_xor_sync(0xFFFFFFFFu, v3, 1);
                #pragma unroll
                for (int half = 0; half < 2; half++) {
                    int r = row + 8 * half;
                    float a = (float)(r & 2047) * inv;
                    float cs = cosf(a), sn = sinf(a);
                    float a0 = half ? v2 : v0, a1 = half ? v3 : v1;
                    float b0 = half ? p2 : p0, b1 = half ? p3 : p1;
                    float xr, xi, xj, xk;
                    if (evn) { xr = a0; xi = a1; xj = b0; xk = b1; }
                    else     { xr = b0; xi = b1; xj = a0; xk = a1; }
                    float pr, pi, pj, pk;
                    qrot(cs, sn, ax, xr, xi, xj, xk, pr, pi, pj, pk);
                    float o0 = evn ? pr : pj, o1 = evn ? pi : pk;
                    if (z == 0) {
                        *(uint32_t*)&Q1[(size_t)r * DIM + col] =
                            packf16(o0 * QSCALE, o1 * QSCALE);
                    } else {
                        uint32_t h, l;
                        splitf16(o0, o1, h, l);
                        *(uint32_t*)&Kh[(size_t)r * DIM + col] = h;
                        *(uint32_t*)&Kl[(size_t)r * DIM + col] = l;
                    }
                }
            }
        }
    }
}

// ================= O-projection GEMM (fp32 out) ============================
__global__ __launch_bounds__(256) void o_gemm(
    const __half* __restrict__ A1,
    const __half* __restrict__ Bh, const __half* __restrict__ Bl,
    const float* __restrict__ bias, float* __restrict__ C) {
    extern __shared__ uint32_t smu[];
    const uint32_t sbase = smem_to_u32(smu);
    const int tid  = threadIdx.x;
    const int lane = tid & 31, wid = tid >> 5;
    const int g = lane >> 2, t = lane & 3;
    const int wm = wid & 1, wn = wid >> 1;
    const int bm = blockIdx.y * 128, bn = blockIdx.x * 128;

    float acc[4][4][4];
    #pragma unroll
    for (int i = 0; i < 4; i++)
        #pragma unroll
        for (int j = 0; j < 4; j++)
            #pragma unroll
            for (int q = 0; q < 4; q++) acc[i][j][q] = 0.f;

    const int crow0 = tid >> 2;
    const int ccol  = tid & 3;
    gemm_core(A1 + (size_t)(bm + crow0) * DIM + ccol * 8,
              Bh + (size_t)(bn + crow0) * DIM + ccol * 8,
              Bl + (size_t)(bn + crow0) * DIM + ccol * 8,
              sbase, smu,
              (uint32_t)(crow0 * SMS + ccol * 4) * 4,
              (uint32_t)(64 * SMS) * 4,
              wm, wn, g, t, acc);

    #pragma unroll
    for (int mi = 0; mi < 4; mi++) {
        int row = bm + wm * 64 + mi * 16 + g;
        #pragma unroll
        for (int nj = 0; nj < 4; nj++) {
            int col = bn + wn * 32 + nj * 8 + 2 * t;
            float bx = bias[col], by = bias[col + 1];
            float2 v;
            v.x = acc[mi][nj][0] + bx; v.y = acc[mi][nj][1] + by;
            *(float2*)&C[(size_t)row * DIM + col] = v;
            v.x = acc[mi][nj][2] + bx; v.y = acc[mi][nj][3] + by;
            *(float2*)&C[(size_t)(row + 8) * DIM + col] = v;
        }
    }
}

// ================= tensor-core causal flash attention ======================
// 128q x 64k tiles, 8 warps, Q single fp16 in regs, K/V fp16 hi/lo,
// 2-product MMA everywhere, double-buffered K/V, 2 CTAs/SM.
// Stage (36864B): Kh@0, Kl@9216, Vh@18432, Vl@27648; 144B rows.
#define ATT_STRIDE 144
#define ATT_STAGE  36864
#define ATT_SMEM   (2 * ATT_STAGE)      /* 73728 */
__global__ __launch_bounds__(256, 2) void attn_tc(
    const __half* __restrict__ Q1,
    const __half* __restrict__ Kh, const __half* __restrict__ Kl,
    const __half* __restrict__ Vh, const __half* __restrict__ Vl,
    __half* __restrict__ O1) {
    extern __shared__ __align__(16) char sm[];
    const uint32_t sb = smem_to_u32(sm);
    const int tid = threadIdx.x, lane = tid & 31, wid = tid >> 5;
    const int g = lane >> 2, t = lane & 3;
    const int qt = (int)gridDim.x - 1 - (int)blockIdx.x;   // heavy blocks first
    const int bh = blockIdx.y;
    const int b = bh >> 4, h = bh & 15;
    const int qb = qt * 128;
    const size_t rbase = (size_t)b * SQ;
    const int hoff = h * DH;

    // ---- stage Q tile into stage0 region, extract fragments to regs ----
    #pragma unroll
    for (int i = 0; i < 4; i++) {
        int rem = tid + 256 * i;              // 0..1023
        int r = rem >> 3, c = rem & 7;
        cp_async16(sb + r * ATT_STRIDE + c * 16,
                   Q1 + (rbase + qb + r) * DIM + hoff + c * 8);
    }
    CP_COMMIT(); CP_WAIT(0);
    __syncthreads();

    uint32_t qf[4][4];
    {
        uint32_t abase = sb + (wid * 16 + (lane & 15)) * ATT_STRIDE + (lane >> 4) * 16;
        #pragma unroll
        for (int kc = 0; kc < 4; kc++)
            ldmatrix_x4(qf[kc], abase + kc * 32);
    }
    __syncthreads();

    float Oa[8][4];
    #pragma unroll
    for (int j = 0; j < 8; j++)
        #pragma unroll
        for (int e = 0; e < 4; e++) Oa[j][e] = 0.f;
    float m0 = -1e30f, m1 = -1e30f, l0 = 0.f, l1 = 0.f;
    const int r0 = qb + wid * 16 + g;
    const int ntiles = 2 * qt + 2;

    const __half* kv0 = Kh + rbase * DIM + hoff;
    const __half* kv1 = Kl + rbase * DIM + hoff;
    const __half* kv2 = Vh + rbase * DIM + hoff;
    const __half* kv3 = Vl + rbase * DIM + hoff;

    #define ISSUE_KV(jt_, st_) do {                                             \
        int _kb = (jt_) * 64;                                                   \
        uint32_t _s = sb + (uint32_t)(st_) * ATT_STAGE;                         \
        _Pragma("unroll")                                                       \
        for (int i = 0; i < 8; i++) {                                           \
            int rem = (i & 1) ? tid + 256 : tid;                                \
            int r = rem >> 3, c = rem & 7;                                      \
            const __half* src =                                                 \
                (i >> 1) == 0 ? kv0 : (i >> 1) == 1 ? kv1 :                     \
                (i >> 1) == 2 ? kv2 : kv3;                                      \
            cp_async16(_s + (i >> 1) * 9216 + r * ATT_STRIDE + c * 16,          \
                       src + (size_t)(_kb + r) * DIM + c * 8);                  \
        }                                                                       \
        CP_COMMIT();                                                            \
    } while (0)

    ISSUE_KV(0, 0);

    for (int jt = 0; jt < ntiles; jt++) {
        const int kb = jt * 64;
        const int cb = jt & 1, nb = cb ^ 1;
        if (jt + 1 < ntiles) {
            ISSUE_KV(jt + 1, nb);
            CP_WAIT(1);
        } else {
            CP_WAIT(0);
        }
        __syncthreads();
        const uint32_t stg = sb + (uint32_t)cb * ATT_STAGE;

        // ---- S = Q (Kh + Kl)^T : 2 products ----
        float S[8][4];
        #pragma unroll
        for (int j = 0; j < 8; j++)
            #pragma unroll
            for (int e = 0; e < 4; e++) S[j][e] = 0.f;

        #pragma unroll
        for (int kc = 0; kc < 4; kc++) {
            uint32_t kaddr = stg + (lane & 7) * ATT_STRIDE + kc * 32 + ((lane >> 3) & 1) * 16;
            #pragma unroll
            for (int j = 0; j < 8; j++) {
                uint32_t bkh[2], bkl[2];
                ldmatrix_x2(bkh, kaddr + j * 8 * ATT_STRIDE);
                ldmatrix_x2(bkl, kaddr + j * 8 * ATT_STRIDE + 9216);
                mma16816h(S[j], qf[kc], bkh);
                mma16816h(S[j], qf[kc], bkl);
            }
        }

        // ---- causal mask (S already scaled via Q) ----
        if (kb + 63 > qb) {
            #pragma unroll
            for (int j = 0; j < 8; j++) {
                int k0 = kb + 8 * j + 2 * t;
                if (k0     > r0    ) S[j][0] = -1e30f;
                if (k0 + 1 > r0    ) S[j][1] = -1e30f;
                if (k0     > r0 + 8) S[j][2] = -1e30f;
                if (k0 + 1 > r0 + 8) S[j][3] = -1e30f;
            }
        }

        // ---- online softmax (log2 domain) ----
        float tm0 = -1e30f, tm1 = -1e30f;
        #pragma unroll
        for (int j = 0; j < 8; j++) {
            tm0 = fmaxf(tm0, fmaxf(S[j][0], S[j][1]));
            tm1 = fmaxf(tm1, fmaxf(S[j][2], S[j][3]));
        }
        tm0 = fmaxf(tm0, __shfl_xor_sync(0xFFFFFFFFu, tm0, 1));
        tm0 = fmaxf(tm0, __shfl_xor_sync(0xFFFFFFFFu, tm0, 2));
        tm1 = fmaxf(tm1, __shfl_xor_sync(0xFFFFFFFFu, tm1, 1));
        tm1 = fmaxf(tm1, __shfl_xor_sync(0xFFFFFFFFu, tm1, 2));
        float mn0 = fmaxf(m0, tm0), mn1 = fmaxf(m1, tm1);
        float sc0 = ex2f(m0 - mn0), sc1 = ex2f(m1 - mn1);
        m0 = mn0; m1 = mn1;
        l0 *= sc0; l1 *= sc1;
        #pragma unroll
        for (int j = 0; j < 8; j++) {
            Oa[j][0] *= sc0; Oa[j][1] *= sc0;
            Oa[j][2] *= sc1; Oa[j][3] *= sc1;
        }
        #pragma unroll
        for (int j = 0; j < 8; j++) {
            S[j][0] = ex2f(S[j][0] - mn0); l0 += S[j][0];
            S[j][1] = ex2f(S[j][1] - mn0); l0 += S[j][1];
            S[j][2] = ex2f(S[j][2] - mn1); l1 += S[j][2];
            S[j][3] = ex2f(S[j][3] - mn1); l1 += S[j][3];
        }

        // ---- O += P (Vh + Vl) : P single fp16, 2 products ----
        #pragma unroll
        for (int c = 0; c < 4; c++) {
            uint32_t pa[4];
            pa[0] = packf16(S[2*c  ][0], S[2*c  ][1]);
            pa[1] = packf16(S[2*c  ][2], S[2*c  ][3]);
            pa[2] = packf16(S[2*c+1][0], S[2*c+1][1]);
            pa[3] = packf16(S[2*c+1][2], S[2*c+1][3]);
            uint32_t vaddr = stg + 18432 + (16 * c + (lane & 15)) * ATT_STRIDE;
            #pragma unroll
            for (int j = 0; j < 8; j++) {
                uint32_t bvh[2], bvl[2];
                ldmatrix_x2_trans(bvh, vaddr + j * 16);
                ldmatrix_x2_trans(bvl, vaddr + j * 16 + 9216);
                mma16816h(Oa[j], pa, bvh);
                mma16816h(Oa[j], pa, bvl);
            }
        }
        __syncthreads();
    }

    // ---- finalize: write single fp16 ----
    l0 += __shfl_xor_sync(0xFFFFFFFFu, l0, 1);
    l0 += __shfl_xor_sync(0xFFFFFFFFu, l0, 2);
    l1 += __shfl_xor_sync(0xFFFFFFFFu, l1, 1);
    l1 += __shfl_xor_sync(0xFFFFFFFFu, l1, 2);
    float inv0 = 1.f / l0, inv1 = 1.f / l1;
    size_t off0 = (rbase + r0) * DIM + hoff + 2 * t;
    size_t off1 = (rbase + r0 + 8) * DIM + hoff + 2 * t;
    #pragma unroll
    for (int j = 0; j < 8; j++) {
        *(uint32_t*)&O1[off0 + 8 * j] = packf16(Oa[j][0] * inv0, Oa[j][1] * inv0);
        *(uint32_t*)&O1[off1 + 8 * j] = packf16(Oa[j][2] * inv1, Oa[j][3] * inv1);
    }
}

// ---------------- launch ---------------------------------------------------
extern "C" void kernel_launch(void* const* d_in, const int* in_sizes, int n_in,
                              void* d_out, int out_size) {
    const float* x = (const float*)d_in[0];
    // d_in[1] = mask (pure causal triu, ignored)
    const float* q_b = (const float*)d_in[6];
    const float* k_b = (const float*)d_in[11];
    const float* v_b = (const float*)d_in[16];
    const float* o_b = (const float*)d_in[21];

    WPtrs wp;
    for (int pr = 0; pr < 4; pr++)
        for (int cm = 0; cm < 4; cm++)
            wp.w[pr][cm] = (const float*)d_in[2 + 5 * pr + cm];

    __half *wh, *wl, *a1, *q1, *kh, *kl, *vh, *vl;
    cudaGetSymbolAddress((void**)&wh, g_wh);
    cudaGetSymbolAddress((void**)&wl, g_wl);
    cudaGetSymbolAddress((void**)&a1, g_a1);
    cudaGetSymbolAddress((void**)&q1, g_q1);
    cudaGetSymbolAddress((void**)&kh, g_kh);
    cudaGetSymbolAddress((void**)&kl, g_kl);
    cudaGetSymbolAddress((void**)&vh, g_vh);
    cudaGetSymbolAddress((void**)&vl, g_vl);

    cudaFuncSetAttribute(qkv_gemm, cudaFuncAttributeMaxDynamicSharedMemorySize,
                         GEMM_SMEM);
    cudaFuncSetAttribute(o_gemm, cudaFuncAttributeMaxDynamicSharedMemorySize,
                         GEMM_SMEM);
    cudaFuncSetAttribute(attn_tc, cudaFuncAttributeMaxDynamicSharedMemorySize,
                         ATT_SMEM);

    dim3 wgrid((DIM * IQ) / 256, 4);
    build_w_all_kernel<<<wgrid, 256>>>(wp, wh, wl);

    const int sblocks = (MROW * DIM / 4) / 256;
    cvt16_kernel<<<sblocks, 256>>>(x, a1);

    dim3 qkvgrid(DIM / 128, MROW / 128, 3);    // (8, 32, 3)
    qkv_gemm<<<qkvgrid, 256, GEMM_SMEM>>>(a1, wh, wl, q_b, k_b, v_b,
                                          q1, kh, kl, vh, vl);

    dim3 agrid(SQ / 128, BQ * HQ);             // (16, 32)
    attn_tc<<<agrid, 256, ATT_SMEM>>>(q1, kh, kl, vh, vl, a1);

    dim3 ogrid(DIM / 128, MROW / 128);         // (8, 32)
    o_gemm<<<ogrid, 256, GEMM_SMEM>>>(a1,
                                      wh + 3 * (size_t)DIM * DIM,
                                      wl + 3 * (size_t)DIM * DIM,
                                      o_b, (float*)d_out);
}

// round 12
// speedup vs baseline: 2.1877x; 1.5456x over previous
#include <cuda_runtime.h>
#include <cuda_fp16.h>
#include <math.h>
#include <cstdint>

#define BQ   2
#define SQ   2048
#define DIM  1024
#define HQ   16
#define DH   64
#define GQ   16
#define IQ   256
#define MROW (BQ*SQ)   /* 4096 */

// scores*0.125 folded into Q together with log2(e) so softmax uses raw ex2
#define QSCALE 0.18033688011112042f   /* 0.125 * log2(e) */

// ---------------- device scratch (no allocations allowed) ----------------
__device__ __half g_w1[4][DIM*DIM];   // W_eff fp16, [n][k]
__device__ __half g_a1[MROW*DIM];     // activation fp16 (x / attn out)
__device__ __half g_q1[MROW*DIM];     // Q fp16 (rope+scale applied)
__device__ __half g_k1[MROW*DIM];
__device__ __half g_v1[MROW*DIM];

// ---------------- helpers --------------------------------------------------
__device__ __forceinline__ uint32_t smem_to_u32(const void* p) {
    uint32_t a;
    asm("{ .reg .u64 t; cvta.to.shared.u64 t, %1; cvt.u32.u64 %0, t; }"
        : "=r"(a) : "l"(p));
    return a;
}
__device__ __forceinline__ void cp_async16(uint32_t dst, const void* src) {
    asm volatile("cp.async.ca.shared.global [%0], [%1], 16;"
                 :: "r"(dst), "l"(src));
}
#define CP_COMMIT() asm volatile("cp.async.commit_group;" ::: "memory")
#define CP_WAIT(n)  asm volatile("cp.async.wait_group %0;" :: "n"(n) : "memory")

__device__ __forceinline__ float ex2f(float x) {
    float r;
    asm("ex2.approx.f32 %0, %1;" : "=f"(r) : "f"(x));
    return r;
}

__device__ __forceinline__ uint32_t packf16(float x, float y) {
    __half2 h = __floats2half2_rn(x, y);
    return *reinterpret_cast<uint32_t*>(&h);
}

__device__ __forceinline__ void mma16816h(float* c, const uint32_t* a, const uint32_t* b) {
    asm volatile(
        "mma.sync.aligned.m16n8k16.row.col.f32.f16.f16.f32 "
        "{%0,%1,%2,%3}, {%4,%5,%6,%7}, {%8,%9}, {%0,%1,%2,%3};"
        : "+f"(c[0]), "+f"(c[1]), "+f"(c[2]), "+f"(c[3])
        : "r"(a[0]), "r"(a[1]), "r"(a[2]), "r"(a[3]), "r"(b[0]), "r"(b[1]));
}
__device__ __forceinline__ void ldmatrix_x4(uint32_t* r, uint32_t addr) {
    asm volatile("ldmatrix.sync.aligned.m8n8.x4.shared.b16 {%0,%1,%2,%3}, [%4];"
                 : "=r"(r[0]), "=r"(r[1]), "=r"(r[2]), "=r"(r[3]) : "r"(addr));
}
__device__ __forceinline__ void ldmatrix_x2(uint32_t* r, uint32_t addr) {
    asm volatile("ldmatrix.sync.aligned.m8n8.x2.shared.b16 {%0,%1}, [%2];"
                 : "=r"(r[0]), "=r"(r[1]) : "r"(addr));
}
__device__ __forceinline__ void ldmatrix_x2_trans(uint32_t* r, uint32_t addr) {
    asm volatile("ldmatrix.sync.aligned.m8n8.x2.trans.shared.b16 {%0,%1}, [%2];"
                 : "=r"(r[0]), "=r"(r[1]) : "r"(addr));
}

// quaternion rope rotation (reference math, fp32)
__device__ __forceinline__ void qrot(float cs, float sn, int ax,
                                     float xr, float xi, float xj, float xk,
                                     float& pr, float& pi, float& pj, float& pk) {
    float ui = (ax == 0) ? sn : 0.f;
    float uj = (ax == 1) ? sn : 0.f;
    float uk = (ax == 2) ? sn : 0.f;
    pr = cs * xr - ui * xi - uj * xj - uk * xk;
    pi = cs * xi + ui * xr + uj * xk - uk * xj;
    pj = cs * xj - ui * xk + uj * xr + uk * xi;
    pk = cs * xk + ui * xj - uj * xi + uk * xr;
}

// ---------------- build all 4 effective quaternion weights (fp16) ----------
struct WPtrs { const float* w[4][4]; };   // [proj][comp r,i,j,k]
__global__ void build_w_all_kernel(WPtrs wp, __half* __restrict__ WBase) {
    int proj = blockIdx.y;
    int idx = blockIdx.x * blockDim.x + threadIdx.x;   // 0 .. DIM*IQ-1
    int n = idx >> 8;          // 0..1023
    int p = idx & 255;         // 0..255
    int m = n >> 2, c = n & 3;

    int off = m * IQ + p;
    float r = wp.w[proj][0][off], i = wp.w[proj][1][off];
    float j = wp.w[proj][2][off], k = wp.w[proj][3][off];

    float v0, v1, v2, v3;
    switch (c) {
        case 0: v0 =  r; v1 = -i; v2 = -j; v3 = -k; break;
        case 1: v0 =  i; v1 =  r; v2 = -j; v3 =  k; break;
        case 2: v0 =  j; v1 =  i; v2 =  r; v3 = -k; break;
        default: v0 = k; v1 = -i; v2 =  j; v3 =  r; break;
    }

    size_t o = ((size_t)proj * DIM * DIM + (size_t)n * DIM + 4 * p) >> 2;
    ((uint2*)WBase)[o] = make_uint2(packf16(v0, v1), packf16(v2, v3));
}

// ---------------- convert fp32 activation into fp16 -------------------------
__global__ void cvt16_kernel(const float* __restrict__ in,
                             __half* __restrict__ out) {
    int i = blockIdx.x * blockDim.x + threadIdx.x;     // float4 index
    float4 v = ((const float4*)in)[i];
    ((uint2*)out)[i] = make_uint2(packf16(v.x, v.y), packf16(v.z, v.w));
}

// ================= fp16 single-product GEMM core ===========================
// C = A @ B^T, both fp16. Tile 128x128, 8 warps, K-slab 32, double buffered.
// smem per buffer (u32): A@0, B@2560; row stride 20 u32.
#define SMS   20
#define BUFU  5120
#define GEMM_SMEM (2 * BUFU * 4)   /* 40960 */

__device__ __forceinline__ void gemm_core(
    const __half* pA, const __half* pB,
    uint32_t sbase, uint32_t* smu, uint32_t doff0, uint32_t rstep,
    int wm, int wn, int g, int t, float acc[4][4][4]) {

    #define ISSUE_SLAB(s, b) do {                                              \
        int _k0 = (s) * 32;                                                    \
        uint32_t _d = sbase + (uint32_t)(b) * (BUFU * 4) + doff0;              \
        cp_async16(_d,                  pA + _k0);                             \
        cp_async16(_d + rstep,          pA + _k0 + (size_t)64 * DIM);          \
        cp_async16(_d + 2560*4,         pB + _k0);                             \
        cp_async16(_d + 2560*4 + rstep, pB + _k0 + (size_t)64 * DIM);          \
        CP_COMMIT();                                                           \
    } while (0)

    ISSUE_SLAB(0, 0);

    for (int s = 0; s < 32; s++) {
        const int cb = s & 1, nb = cb ^ 1;
        if (s + 1 < 32) {
            ISSUE_SLAB(s + 1, nb);
            CP_WAIT(1);
        } else {
            CP_WAIT(0);
        }
        __syncthreads();

        const uint32_t* base = smu + cb * BUFU;
        #pragma unroll
        for (int kk = 0; kk < 2; kk++) {
            uint32_t a[4][4];
            #pragma unroll
            for (int mi = 0; mi < 4; mi++) {
                int r0 = (wm * 64 + mi * 16 + g) * SMS + kk * 8 + t;
                a[mi][0] = base[r0];     a[mi][1] = base[r0 + 8 * SMS];
                a[mi][2] = base[r0 + 4]; a[mi][3] = base[r0 + 8 * SMS + 4];
            }
            uint32_t bb[4][2];
            #pragma unroll
            for (int nj = 0; nj < 4; nj++) {
                int rn = (wn * 32 + nj * 8 + g) * SMS + kk * 8 + t;
                bb[nj][0] = base[2560 + rn]; bb[nj][1] = base[2560 + rn + 4];
            }
            #pragma unroll
            for (int mi = 0; mi < 4; mi++)
                #pragma unroll
                for (int nj = 0; nj < 4; nj++)
                    mma16816h(acc[mi][nj], a[mi], bb[nj]);
        }
        __syncthreads();
    }
}

// z = 0: Q (rope + scale); 1: K (rope); 2: V (plain). All fp16 out.
__global__ __launch_bounds__(256) void qkv_gemm(
    const __half* __restrict__ A1, const __half* __restrict__ WBase,
    const float* __restrict__ q_b, const float* __restrict__ k_b,
    const float* __restrict__ v_b,
    __half* __restrict__ Q1, __half* __restrict__ K1, __half* __restrict__ V1) {
    extern __shared__ uint32_t smu[];
    const uint32_t sbase = smem_to_u32(smu);
    const int tid  = threadIdx.x;
    const int lane = tid & 31, wid = tid >> 5;
    const int g = lane >> 2, t = lane & 3;
    const int wm = wid & 1, wn = wid >> 1;
    const int bm = blockIdx.y * 128, bn = blockIdx.x * 128;
    const int z = blockIdx.z;

    const __half* B = WBase + (size_t)z * DIM * DIM;
    const float* bias = (z == 0) ? q_b : (z == 1) ? k_b : v_b;
    __half* C = (z == 0) ? Q1 : (z == 1) ? K1 : V1;

    float acc[4][4][4];
    #pragma unroll
    for (int i = 0; i < 4; i++)
        #pragma unroll
        for (int j = 0; j < 4; j++)
            #pragma unroll
            for (int q = 0; q < 4; q++) acc[i][j][q] = 0.f;

    const int crow0 = tid >> 2;
    const int ccol  = tid & 3;
    gemm_core(A1 + (size_t)(bm + crow0) * DIM + ccol * 8,
              B  + (size_t)(bn + crow0) * DIM + ccol * 8,
              sbase, smu,
              (uint32_t)(crow0 * SMS + ccol * 4) * 4,
              (uint32_t)(64 * SMS) * 4,
              wm, wn, g, t, acc);

    if (z == 2) {
        // ---- V: plain fp16 ----
        #pragma unroll
        for (int mi = 0; mi < 4; mi++) {
            int row = bm + wm * 64 + mi * 16 + g;
            #pragma unroll
            for (int nj = 0; nj < 4; nj++) {
                int col = bn + wn * 32 + nj * 8 + 2 * t;
                float bx = bias[col], by = bias[col + 1];
                *(uint32_t*)&C[(size_t)row * DIM + col] =
                    packf16(acc[mi][nj][0] + bx, acc[mi][nj][1] + by);
                *(uint32_t*)&C[(size_t)(row + 8) * DIM + col] =
                    packf16(acc[mi][nj][2] + bx, acc[mi][nj][3] + by);
            }
        }
    } else {
        // ---- Q/K: fused RoPE; Q also folds softmax scale ----
        const bool evn = (t & 1) == 0;
        const float osc = (z == 0) ? QSCALE : 1.0f;
        #pragma unroll
        for (int nj = 0; nj < 4; nj++) {
            int col = bn + wn * 32 + nj * 8 + 2 * t;
            int grp = (col >> 2) & 15;
            float inv = powf(10000.0f, -(float)grp / 16.0f);
            int ax = grp % 3;
            float bx = bias[col], by = bias[col + 1];
            #pragma unroll
            for (int mi = 0; mi < 4; mi++) {
                int row = bm + wm * 64 + mi * 16 + g;
                float v0 = acc[mi][nj][0] + bx, v1 = acc[mi][nj][1] + by;
                float v2 = acc[mi][nj][2] + bx, v3 = acc[mi][nj][3] + by;
                float p0 = __shfl_xor_sync(0xFFFFFFFFu, v0, 1);
                float p1 = __shfl_xor_sync(0xFFFFFFFFu, v1, 1);
                float p2 = __shfl_xor_sync(0xFFFFFFFFu, v2, 1);
                float p3 = __shfl_xor_sync(0xFFFFFFFFu, v3, 1);
                #pragma unroll
                for (int half = 0; half < 2; half++) {
                    int r = row + 8 * half;
                    float a = (float)(r & 2047) * inv;
                    float cs = cosf(a), sn = sinf(a);
                    float a0 = half ? v2 : v0, a1 = half ? v3 : v1;
                    float b0 = half ? p2 : p0, b1 = half ? p3 : p1;
                    float xr, xi, xj, xk;
                    if (evn) { xr = a0; xi = a1; xj = b0; xk = b1; }
                    else     { xr = b0; xi = b1; xj = a0; xk = a1; }
                    float pr, pi, pj, pk;
                    qrot(cs, sn, ax, xr, xi, xj, xk, pr, pi, pj, pk);
                    float o0 = (evn ? pr : pj) * osc, o1 = (evn ? pi : pk) * osc;
                    *(uint32_t*)&C[(size_t)r * DIM + col] = packf16(o0, o1);
                }
            }
        }
    }
}

// ================= O-projection GEMM (fp32 out) ============================
__global__ __launch_bounds__(256) void o_gemm(
    const __half* __restrict__ A1, const __half* __restrict__ B,
    const float* __restrict__ bias, float* __restrict__ C) {
    extern __shared__ uint32_t smu[];
    const uint32_t sbase = smem_to_u32(smu);
    const int tid  = threadIdx.x;
    const int lane = tid & 31, wid = tid >> 5;
    const int g = lane >> 2, t = lane & 3;
    const int wm = wid & 1, wn = wid >> 1;
    const int bm = blockIdx.y * 128, bn = blockIdx.x * 128;

    float acc[4][4][4];
    #pragma unroll
    for (int i = 0; i < 4; i++)
        #pragma unroll
        for (int j = 0; j < 4; j++)
            #pragma unroll
            for (int q = 0; q < 4; q++) acc[i][j][q] = 0.f;

    const int crow0 = tid >> 2;
    const int ccol  = tid & 3;
    gemm_core(A1 + (size_t)(bm + crow0) * DIM + ccol * 8,
              B  + (size_t)(bn + crow0) * DIM + ccol * 8,
              sbase, smu,
              (uint32_t)(crow0 * SMS + ccol * 4) * 4,
              (uint32_t)(64 * SMS) * 4,
              wm, wn, g, t, acc);

    #pragma unroll
    for (int mi = 0; mi < 4; mi++) {
        int row = bm + wm * 64 + mi * 16 + g;
        #pragma unroll
        for (int nj = 0; nj < 4; nj++) {
            int col = bn + wn * 32 + nj * 8 + 2 * t;
            float bx = bias[col], by = bias[col + 1];
            float2 v;
            v.x = acc[mi][nj][0] + bx; v.y = acc[mi][nj][1] + by;
            *(float2*)&C[(size_t)row * DIM + col] = v;
            v.x = acc[mi][nj][2] + bx; v.y = acc[mi][nj][3] + by;
            *(float2*)&C[(size_t)(row + 8) * DIM + col] = v;
        }
    }
}

// ================= tensor-core causal flash attention ======================
// 128q x 64k tiles, 8 warps, all fp16 single product, double-buffered K/V,
// 2 CTAs/SM. Stage (18432B): K@0, V@9216; 144B rows.
#define ATT_STRIDE 144
#define ATT_STAGE  18432
#define ATT_SMEM   (2 * ATT_STAGE)      /* 36864 */
__global__ __launch_bounds__(256, 2) void attn_tc(
    const __half* __restrict__ Q1,
    const __half* __restrict__ K1, const __half* __restrict__ V1,
    __half* __restrict__ O1) {
    extern __shared__ __align__(16) char sm[];
    const uint32_t sb = smem_to_u32(sm);
    const int tid = threadIdx.x, lane = tid & 31, wid = tid >> 5;
    const int g = lane >> 2, t = lane & 3;
    const int qt = (int)gridDim.x - 1 - (int)blockIdx.x;   // heavy blocks first
    const int bh = blockIdx.y;
    const int b = bh >> 4, h = bh & 15;
    const int qb = qt * 128;
    const size_t rbase = (size_t)b * SQ;
    const int hoff = h * DH;

    // ---- stage Q tile into full smem region, extract fragments to regs ----
    #pragma unroll
    for (int i = 0; i < 4; i++) {
        int rem = tid + 256 * i;              // 0..1023
        int r = rem >> 3, c = rem & 7;
        cp_async16(sb + r * ATT_STRIDE + c * 16,
                   Q1 + (rbase + qb + r) * DIM + hoff + c * 8);
    }
    CP_COMMIT(); CP_WAIT(0);
    __syncthreads();

    uint32_t qf[4][4];
    {
        uint32_t abase = sb + (wid * 16 + (lane & 15)) * ATT_STRIDE + (lane >> 4) * 16;
        #pragma unroll
        for (int kc = 0; kc < 4; kc++)
            ldmatrix_x4(qf[kc], abase + kc * 32);
    }
    __syncthreads();

    float Oa[8][4];
    #pragma unroll
    for (int j = 0; j < 8; j++)
        #pragma unroll
        for (int e = 0; e < 4; e++) Oa[j][e] = 0.f;
    float m0 = -1e30f, m1 = -1e30f, l0 = 0.f, l1 = 0.f;
    const int r0 = qb + wid * 16 + g;
    const int ntiles = 2 * qt + 2;

    const __half* kvK = K1 + rbase * DIM + hoff;
    const __half* kvV = V1 + rbase * DIM + hoff;

    #define ISSUE_KV(jt_, st_) do {                                             \
        int _kb = (jt_) * 64;                                                   \
        uint32_t _s = sb + (uint32_t)(st_) * ATT_STAGE;                         \
        _Pragma("unroll")                                                       \
        for (int i = 0; i < 4; i++) {                                           \
            int rem = (i & 1) ? tid + 256 : tid;                                \
            int r = rem >> 3, c = rem & 7;                                      \
            const __half* src = (i >> 1) == 0 ? kvK : kvV;                      \
            cp_async16(_s + (i >> 1) * 9216 + r * ATT_STRIDE + c * 16,          \
                       src + (size_t)(_kb + r) * DIM + c * 8);                  \
        }                                                                       \
        CP_COMMIT();                                                            \
    } while (0)

    ISSUE_KV(0, 0);

    for (int jt = 0; jt < ntiles; jt++) {
        const int kb = jt * 64;
        const int cb = jt & 1, nb = cb ^ 1;
        if (jt + 1 < ntiles) {
            ISSUE_KV(jt + 1, nb);
            CP_WAIT(1);
        } else {
            CP_WAIT(0);
        }
        __syncthreads();
        const uint32_t stg = sb + (uint32_t)cb * ATT_STAGE;

        // ---- S = Q K^T : single product ----
        float S[8][4];
        #pragma unroll
        for (int j = 0; j < 8; j++)
            #pragma unroll
            for (int e = 0; e < 4; e++) S[j][e] = 0.f;

        #pragma unroll
        for (int kc = 0; kc < 4; kc++) {
            uint32_t kaddr = stg + (lane & 7) * ATT_STRIDE + kc * 32 + ((lane >> 3) & 1) * 16;
            #pragma unroll
            for (int j = 0; j < 8; j++) {
                uint32_t bk[2];
                ldmatrix_x2(bk, kaddr + j * 8 * ATT_STRIDE);
                mma16816h(S[j], qf[kc], bk);
            }
        }

        // ---- causal mask (S already scaled via Q) ----
        if (kb + 63 > qb) {
            #pragma unroll
            for (int j = 0; j < 8; j++) {
                int k0 = kb + 8 * j + 2 * t;
                if (k0     > r0    ) S[j][0] = -1e30f;
                if (k0 + 1 > r0    ) S[j][1] = -1e30f;
                if (k0     > r0 + 8) S[j][2] = -1e30f;
                if (k0 + 1 > r0 + 8) S[j][3] = -1e30f;
            }
        }

        // ---- online softmax (log2 domain) ----
        float tm0 = -1e30f, tm1 = -1e30f;
        #pragma unroll
        for (int j = 0; j < 8; j++) {
            tm0 = fmaxf(tm0, fmaxf(S[j][0], S[j][1]));
            tm1 = fmaxf(tm1, fmaxf(S[j][2], S[j][3]));
        }
        tm0 = fmaxf(tm0, __shfl_xor_sync(0xFFFFFFFFu, tm0, 1));
        tm0 = fmaxf(tm0, __shfl_xor_sync(0xFFFFFFFFu, tm0, 2));
        tm1 = fmaxf(tm1, __shfl_xor_sync(0xFFFFFFFFu, tm1, 1));
        tm1 = fmaxf(tm1, __shfl_xor_sync(0xFFFFFFFFu, tm1, 2));
        float mn0 = fmaxf(m0, tm0), mn1 = fmaxf(m1, tm1);
        float sc0 = ex2f(m0 - mn0), sc1 = ex2f(m1 - mn1);
        m0 = mn0; m1 = mn1;
        l0 *= sc0; l1 *= sc1;
        #pragma unroll
        for (int j = 0; j < 8; j++) {
            Oa[j][0] *= sc0; Oa[j][1] *= sc0;
            Oa[j][2] *= sc1; Oa[j][3] *= sc1;
        }
        #pragma unroll
        for (int j = 0; j < 8; j++) {
            S[j][0] = ex2f(S[j][0] - mn0); l0 += S[j][0];
            S[j][1] = ex2f(S[j][1] - mn0); l0 += S[j][1];
            S[j][2] = ex2f(S[j][2] - mn1); l1 += S[j][2];
            S[j][3] = ex2f(S[j][3] - mn1); l1 += S[j][3];
        }

        // ---- O += P V : single product ----
        #pragma unroll
        for (int c = 0; c < 4; c++) {
            uint32_t pa[4];
            pa[0] = packf16(S[2*c  ][0], S[2*c  ][1]);
            pa[1] = packf16(S[2*c  ][2], S[2*c  ][3]);
            pa[2] = packf16(S[2*c+1][0], S[2*c+1][1]);
            pa[3] = packf16(S[2*c+1][2], S[2*c+1][3]);
            uint32_t vaddr = stg + 9216 + (16 * c + (lane & 15)) * ATT_STRIDE;
            #pragma unroll
            for (int j = 0; j < 8; j++) {
                uint32_t bv[2];
                ldmatrix_x2_trans(bv, vaddr + j * 16);
                mma16816h(Oa[j], pa, bv);
            }
        }
        __syncthreads();
    }

    // ---- finalize: write fp16 ----
    l0 += __shfl_xor_sync(0xFFFFFFFFu, l0, 1);
    l0 += __shfl_xor_sync(0xFFFFFFFFu, l0, 2);
    l1 += __shfl_xor_sync(0xFFFFFFFFu, l1, 1);
    l1 += __shfl_xor_sync(0xFFFFFFFFu, l1, 2);
    float inv0 = 1.f / l0, inv1 = 1.f / l1;
    size_t off0 = (rbase + r0) * DIM + hoff + 2 * t;
    size_t off1 = (rbase + r0 + 8) * DIM + hoff + 2 * t;
    #pragma unroll
    for (int j = 0; j < 8; j++) {
        *(uint32_t*)&O1[off0 + 8 * j] = packf16(Oa[j][0] * inv0, Oa[j][1] * inv0);
        *(uint32_t*)&O1[off1 + 8 * j] = packf16(Oa[j][2] * inv1, Oa[j][3] * inv1);
    }
}

// ---------------- launch ---------------------------------------------------
extern "C" void kernel_launch(void* const* d_in, const int* in_sizes, int n_in,
                              void* d_out, int out_size) {
    const float* x = (const float*)d_in[0];
    // d_in[1] = mask (pure causal triu, ignored)
    const float* q_b = (const float*)d_in[6];
    const float* k_b = (const float*)d_in[11];
    const float* v_b = (const float*)d_in[16];
    const float* o_b = (const float*)d_in[21];

    WPtrs wp;
    for (int pr = 0; pr < 4; pr++)
        for (int cm = 0; cm < 4; cm++)
            wp.w[pr][cm] = (const float*)d_in[2 + 5 * pr + cm];

    __half *w1, *a1, *q1, *k1, *v1;
    cudaGetSymbolAddress((void**)&w1, g_w1);
    cudaGetSymbolAddress((void**)&a1, g_a1);
    cudaGetSymbolAddress((void**)&q1, g_q1);
    cudaGetSymbolAddress((void**)&k1, g_k1);
    cudaGetSymbolAddress((void**)&v1, g_v1);

    cudaFuncSetAttribute(qkv_gemm, cudaFuncAttributeMaxDynamicSharedMemorySize,
                         GEMM_SMEM);
    cudaFuncSetAttribute(o_gemm, cudaFuncAttributeMaxDynamicSharedMemorySize,
                         GEMM_SMEM);
    cudaFuncSetAttribute(attn_tc, cudaFuncAttributeMaxDynamicSharedMemorySize,
                         ATT_SMEM);

    dim3 wgrid((DIM * IQ) / 256, 4);
    build_w_all_kernel<<<wgrid, 256>>>(wp, w1);

    const int sblocks = (MROW * DIM / 4) / 256;
    cvt16_kernel<<<sblocks, 256>>>(x, a1);

    dim3 qkvgrid(DIM / 128, MROW / 128, 3);    // (8, 32, 3)
    qkv_gemm<<<qkvgrid, 256, GEMM_SMEM>>>(a1, w1, q_b, k_b, v_b, q1, k1, v1);

    dim3 agrid(SQ / 128, BQ * HQ);             // (16, 32)
    attn_tc<<<agrid, 256, ATT_SMEM>>>(q1, k1, v1, a1);

    dim3 ogrid(DIM / 128, MROW / 128);         // (8, 32)
    o_gemm<<<ogrid, 256, GEMM_SMEM>>>(a1, w1 + 3 * (size_t)DIM * DIM,
                                      o_b, (float*)d_out);
}